// round 9
// baseline (speedup 1.0000x reference)
#include <cuda_runtime.h>
#include <math.h>
#include <stdint.h>

#define TOKENS 32768
#define LSEQ   512
#define HID    128
#define VD     256
#define FFND   256
#define QKN    768   // 128 Q | 128 K | 256 V | 256 G

// fp32 row-major buffers
__device__ float g_X [TOKENS * HID];
__device__ float g_Y1[TOKENS * HID];
__device__ float g_QK[(size_t)TOKENS * QKN];
// fragment-major (tf32 bits) operand buffers
__device__ float g_Xn[TOKENS * HID];
__device__ float g_P [TOKENS * VD];
__device__ float g_Hf[TOKENS * FFND];
__device__ float g_Wq[4 * HID * QKN];
__device__ float g_Wo[4 * VD * HID];
__device__ float g_W1[4 * HID * FFND];
__device__ float g_W2[4 * FFND * HID];
__device__ float g_qc[LSEQ*16], g_qs[LSEQ*16], g_kc[LSEQ*16], g_ks[LSEQ*16];

__device__ __forceinline__ float geluf(float v){ return 0.5f*v*(1.0f+erff(v*0.70710678f)); }
__device__ __forceinline__ float siluf(float v){ return v/(1.0f+expf(-v)); }
__device__ __forceinline__ unsigned tf32r(float x){
    unsigned r; asm("cvt.rna.tf32.f32 %0, %1;" : "=r"(r) : "f"(x)); return r;
}
__device__ __forceinline__ void mma_tf32(float* d, const unsigned* a, const unsigned* b){
    asm volatile("mma.sync.aligned.m16n8k8.row.col.f32.tf32.tf32.f32 "
        "{%0,%1,%2,%3},{%4,%5,%6,%7},{%8,%9},{%0,%1,%2,%3};"
        : "+f"(d[0]),"+f"(d[1]),"+f"(d[2]),"+f"(d[3])
        : "r"(a[0]),"r"(a[1]),"r"(a[2]),"r"(a[3]), "r"(b[0]),"r"(b[1]));
}

// A-fragment index for element (row, k), contract dim K (K8 = K>>3)
__device__ __forceinline__ size_t a_idx(int row, int k, int K8){
    return ((size_t)((row>>4)*K8 + (k>>3)))*128 + (size_t)((row&7)*16 + (k&3)*4
           + ((row>>3)&1) + (((k>>2)&1)<<1));
}
// B-fragment index for element (k, n)
__device__ __forceinline__ size_t b_idx(int k, int n, int K8){
    return ((size_t)((n>>3)*K8 + (k>>3)))*64 + (size_t)((n&7)*8 + (k&3)*2 + ((k>>2)&1));
}

// ------------------- xpos tables -------------------
__global__ void xpos_table_kernel(){
    int idx = blockIdx.x*256 + threadIdx.x;
    if (idx >= LSEQ*16) return;
    int l = idx >> 4, j = idx & 15;
    float base = ((float)j + 12.8f) / 44.8f;
    float sc   = powf(base, (float)l / 512.0f);
    float ang  = (float)l * powf(10000.0f, -(float)j/16.0f);
    float s, c; sincosf(ang, &s, &c);
    g_qc[idx]=c*sc; g_qs[idx]=s*sc; g_kc[idx]=c/sc; g_ks[idx]=s/sc;
}

// ------------------- ALL weights -> B-fragment layout (tf32), one launch -------------------
__global__ void wfrag_all_kernel(
    const float* __restrict__ wq, const float* __restrict__ wk,
    const float* __restrict__ wv, const float* __restrict__ wg,
    const float* __restrict__ wo, const float* __restrict__ w1,
    const float* __restrict__ w2)
{
    int idx = blockIdx.x*256 + threadIdx.x;           // < 4*196608
    int l = idx / 196608, r = idx % 196608;
    if (r < 98304){
        int k = r / QKN, n = r % QKN;
        float v;
        if (n < 128)      v = wq[(((size_t)l*4 + (n>>5))*HID + k)*32 + (n&31)];
        else if (n < 256) { int c=n-128; v = wk[(((size_t)l*4 + (c>>5))*HID + k)*32 + (c&31)]; }
        else if (n < 512) { int c=n-256; v = wv[(((size_t)l*4 + (c>>6))*HID + k)*64 + (c&63)]; }
        else              v = wg[((size_t)l*HID + k)*VD + (n-512)];
        g_Wq[(size_t)l*HID*QKN + b_idx(k, n, 16)] = __uint_as_float(tf32r(v));
    } else {
        int r2 = r - 98304;
        int m = r2 >> 15, e = r2 & 32767;
        if (m == 0){
            int k = e >> 7, n = e & 127;               // wo: K=256, N=128
            g_Wo[(size_t)l*VD*HID + b_idx(k, n, 32)] =
                __uint_as_float(tf32r(wo[(size_t)l*VD*HID + (size_t)k*HID + n]));
        } else if (m == 1){
            int k = e >> 8, n = e & 255;               // ffn1: K=128, N=256
            g_W1[(size_t)l*HID*FFND + b_idx(k, n, 16)] =
                __uint_as_float(tf32r(w1[(size_t)l*HID*FFND + (size_t)k*FFND + n]));
        } else {
            int k = e >> 7, n = e & 127;               // ffn2: K=256, N=128
            g_W2[(size_t)l*FFND*HID + b_idx(k, n, 32)] =
                __uint_as_float(tf32r(w2[(size_t)l*FFND*HID + (size_t)k*HID + n]));
        }
    }
}

// ------------------- input MLP -------------------
__global__ __launch_bounds__(256) void rem_kernel(
    const float* __restrict__ x,
    const float* __restrict__ w1, const float* __restrict__ b1,
    const float* __restrict__ w2, const float* __restrict__ b2,
    const float* __restrict__ w3, const float* __restrict__ b3,
    float* __restrict__ X)
{
    __shared__ float sw1[160], sb1[32], sw2[2048], sb2[64], sw3[8192], sb3[128];
    int tid = threadIdx.x;
    for (int i=tid;i<160; i+=256) sw1[i]=w1[i];
    for (int i=tid;i<2048;i+=256) sw2[i]=w2[i];
    for (int i=tid;i<8192;i+=256) sw3[i]=w3[i];
    if (tid<32)  sb1[tid]=b1[tid];
    if (tid<64)  sb2[tid]=b2[tid];
    if (tid<128) sb3[tid]=b3[tid];
    __syncthreads();
    int t = blockIdx.x*256 + tid;
    float xin[5];
#pragma unroll
    for (int k=0;k<5;k++) xin[k] = x[(size_t)t*5+k];
    float h1[32];
#pragma unroll
    for (int o=0;o<32;o++){ float s=sb1[o];
#pragma unroll
        for (int k=0;k<5;k++) s += xin[k]*sw1[k*32+o];
        h1[o]=geluf(s); }
    float h2[64];
#pragma unroll
    for (int o=0;o<64;o++){ float s=sb2[o];
#pragma unroll
        for (int k=0;k<32;k++) s += h1[k]*sw2[k*64+o];
        h2[o]=geluf(s); }
    for (int o=0;o<128;o+=4){
        float v0=sb3[o],v1=sb3[o+1],v2=sb3[o+2],v3=sb3[o+3];
#pragma unroll
        for (int k=0;k<64;k++){ float hk=h2[k];
            v0+=hk*sw3[k*128+o]; v1+=hk*sw3[k*128+o+1];
            v2+=hk*sw3[k*128+o+2]; v3+=hk*sw3[k*128+o+3]; }
        *(float4*)(X+(size_t)t*128+o) = make_float4(geluf(v0),geluf(v1),geluf(v2),geluf(v3));
    }
}

// ------------------- LayerNorm(128) -> A-fragment layout (entry only) -------------------
__global__ __launch_bounds__(256) void ln_frag_kernel(
    const float* __restrict__ X, const float* __restrict__ w,
    const float* __restrict__ b, float* __restrict__ out)
{
    int g = blockIdx.x*256 + threadIdx.x;
    int row = g>>5, lane = g&31;
    float4 v = *(const float4*)(X + (size_t)row*128 + lane*4);
    float s = v.x+v.y+v.z+v.w;
    float s2 = v.x*v.x+v.y*v.y+v.z*v.z+v.w*v.w;
#pragma unroll
    for (int o=16;o;o>>=1){ s += __shfl_xor_sync(~0u,s,o); s2 += __shfl_xor_sync(~0u,s2,o); }
    float mean = s*(1.f/128.f), var = s2*(1.f/128.f)-mean*mean;
    float rstd = rsqrtf(var + 1e-5f);
    float4 wv = *(const float4*)(w+lane*4), bv = *(const float4*)(b+lane*4);
    float rv[4];
    rv[0]=(v.x-mean)*rstd*wv.x+bv.x; rv[1]=(v.y-mean)*rstd*wv.y+bv.y;
    rv[2]=(v.z-mean)*rstd*wv.z+bv.z; rv[3]=(v.w-mean)*rstd*wv.w+bv.w;
#pragma unroll
    for (int j=0;j<4;j++){
        int k = lane*4 + j;
        out[a_idx(row, k, 16)] = __uint_as_float(tf32r(rv[j]));
    }
}

// ------------------- fragment-fed tf32 tensor-core GEMM (128x64 tile) -------------------
template<int OP>
__global__ __launch_bounds__(256) void gemm_f(
    const float* __restrict__ Af, const float* __restrict__ Bf,
    const float* __restrict__ bias, const float* __restrict__ R,
    float* __restrict__ Cf, float* __restrict__ Ca, int N, int K)
{
    const int tid = threadIdx.x, lane = tid & 31, wid = tid >> 5;
    const int wm = wid & 3, wn = wid >> 2;
    const int m0 = blockIdx.y*128, n0 = blockIdx.x*64;
    const int K8 = K >> 3;

    float acc[2][4][4];
#pragma unroll
    for (int i=0;i<2;i++)
#pragma unroll
        for (int j=0;j<4;j++)
#pragma unroll
            for (int u=0;u<4;u++) acc[i][j][u]=0.f;

    const float* Ab = Af + ((size_t)((m0>>4) + wm*2))*K8*128 + lane*4;
    const float* Bb = Bf + ((size_t)((n0>>3) + wn*4))*K8*64  + lane*2;

#pragma unroll 2
    for (int kc = 0; kc < K8; kc++){
        unsigned a[2][4], b[4][2];
#pragma unroll
        for (int mi=0;mi<2;mi++){
            uint4 t = *(const uint4*)(Ab + ((size_t)mi*K8 + kc)*128);
            a[mi][0]=t.x; a[mi][1]=t.y; a[mi][2]=t.z; a[mi][3]=t.w;
        }
#pragma unroll
        for (int ni=0;ni<4;ni++){
            uint2 t = *(const uint2*)(Bb + ((size_t)ni*K8 + kc)*64);
            b[ni][0]=t.x; b[ni][1]=t.y;
        }
#pragma unroll
        for (int mi=0;mi<2;mi++)
#pragma unroll
            for (int ni=0;ni<4;ni++)
                mma_tf32(acc[mi][ni], a[mi], b[ni]);
    }

    const int gid = lane>>2, tig = lane&3;
#pragma unroll
    for (int mi=0;mi<2;mi++)
#pragma unroll
        for (int ni=0;ni<4;ni++){
            int col = n0 + wn*32 + ni*8 + tig*2;
            float bb0=0.f, bb1=0.f;
            if (bias){ float2 bv = *(const float2*)(bias+col); bb0=bv.x; bb1=bv.y; }
#pragma unroll
            for (int hh=0; hh<2; hh++){
                int row = m0 + wm*32 + mi*16 + gid + hh*8;
                float v0 = acc[mi][ni][hh*2+0] + bb0;
                float v1 = acc[mi][ni][hh*2+1] + bb1;
                if (OP==1){
                    v0 = geluf(v0); v1 = geluf(v1);
                    int K8o = N >> 3;
                    Ca[a_idx(row, col,   K8o)] = __uint_as_float(tf32r(v0));
                    Ca[a_idx(row, col+1, K8o)] = __uint_as_float(tf32r(v1));
                } else {
                    if (OP==3){ float2 rv = *(const float2*)(R + (size_t)row*N + col);
                                v0+=rv.x; v1+=rv.y; }
                    if (OP==2 && col < 256){
                        int l = row & 511;
                        const float* ct = (col<128)? g_qc : g_kc;
                        const float* st = (col<128)? g_qs : g_ks;
                        int j = (col&31)>>1;
                        float c0=ct[l*16+j], s0=st[l*16+j];
                        float t0 = v0*c0 - v1*s0, t1 = v1*c0 + v0*s0;
                        v0=t0; v1=t1;
                    }
                    *(float2*)(Cf + (size_t)row*N + col) = make_float2(v0,v1);
                }
            }
        }
}

// ------------------- fused GEMM(N=128) + residual + LayerNorm -------------------
// C = A@B [+bias] + R ; Xout = C (fp32) ; Fout = A-frag(tf32) of LN(C, lw, lb).
// Block tile 128x128: 8 warps, warp wm owns rows m0+wm*16..+15, all 128 cols.
__global__ __launch_bounds__(256) void gemm_ln(
    const float* __restrict__ Af, const float* __restrict__ Bf,
    const float* __restrict__ bias, const float* __restrict__ R,
    const float* __restrict__ lw, const float* __restrict__ lb,
    float* __restrict__ Xout, float* __restrict__ Fout, int K)
{
    const int tid = threadIdx.x, lane = tid & 31, wm = tid >> 5;
    const int m0 = blockIdx.x*128;
    const int K8 = K >> 3;

    float acc[16][4];
#pragma unroll
    for (int j=0;j<16;j++)
#pragma unroll
        for (int u=0;u<4;u++) acc[j][u]=0.f;

    const float* Ab = Af + ((size_t)((m0>>4) + wm))*K8*128 + lane*4;
    const float* Bb = Bf + lane*2;

    for (int kc = 0; kc < K8; kc++){
        unsigned a[4];
        uint4 t = *(const uint4*)(Ab + (size_t)kc*128);
        a[0]=t.x; a[1]=t.y; a[2]=t.z; a[3]=t.w;
#pragma unroll
        for (int ni=0;ni<16;ni++){
            uint2 bt = *(const uint2*)(Bb + ((size_t)ni*K8 + kc)*64);
            unsigned bfr[2] = {bt.x, bt.y};
            mma_tf32(acc[ni], a, bfr);
        }
    }

    const int gid = lane>>2, tig = lane&3;
    float sum[2]={0.f,0.f}, ssq[2]={0.f,0.f};
#pragma unroll
    for (int ni=0;ni<16;ni++){
        int col = ni*8 + tig*2;
        float bb0=0.f, bb1=0.f;
        if (bias){ float2 bv = *(const float2*)(bias+col); bb0=bv.x; bb1=bv.y; }
#pragma unroll
        for (int hh=0; hh<2; hh++){
            int row = m0 + wm*16 + gid + hh*8;
            float2 rv = *(const float2*)(R + (size_t)row*128 + col);
            float v0 = acc[ni][hh*2+0] + bb0 + rv.x;
            float v1 = acc[ni][hh*2+1] + bb1 + rv.y;
            acc[ni][hh*2+0] = v0; acc[ni][hh*2+1] = v1;
            sum[hh] += v0 + v1;
            ssq[hh] += v0*v0 + v1*v1;
        }
    }
#pragma unroll
    for (int o=1;o<4;o<<=1){
        sum[0] += __shfl_xor_sync(~0u,sum[0],o);
        ssq[0] += __shfl_xor_sync(~0u,ssq[0],o);
        sum[1] += __shfl_xor_sync(~0u,sum[1],o);
        ssq[1] += __shfl_xor_sync(~0u,ssq[1],o);
    }
    float mean[2], rstd[2];
#pragma unroll
    for (int hh=0; hh<2; hh++){
        mean[hh] = sum[hh]*(1.f/128.f);
        float var = ssq[hh]*(1.f/128.f) - mean[hh]*mean[hh];
        rstd[hh] = rsqrtf(var + 1e-5f);
    }
#pragma unroll
    for (int ni=0;ni<16;ni++){
        int col = ni*8 + tig*2;
        float2 lwv = *(const float2*)(lw+col), lbv = *(const float2*)(lb+col);
#pragma unroll
        for (int hh=0; hh<2; hh++){
            int row = m0 + wm*16 + gid + hh*8;
            float v0 = acc[ni][hh*2+0], v1 = acc[ni][hh*2+1];
            *(float2*)(Xout + (size_t)row*128 + col) = make_float2(v0, v1);
            float n0 = (v0-mean[hh])*rstd[hh]*lwv.x + lbv.x;
            float n1 = (v1-mean[hh])*rstd[hh]*lwv.y + lbv.y;
            Fout[a_idx(row, col,   16)] = __uint_as_float(tf32r(n0));
            Fout[a_idx(row, col+1, 16)] = __uint_as_float(tf32r(n1));
        }
    }
}

// ------------------- Retention (128-row q-tiles, mma.sync) + GN + silu -> A-frag P -------------------
#define RET_SMEM (18432*4)
__global__ __launch_bounds__(256) void retention_kernel(
    const float* __restrict__ QKVG, const float* __restrict__ gn_w,
    const float* __restrict__ gn_b, float* __restrict__ P)
{
    extern __shared__ float sm[];
    float* Qf = sm;
    float* Kf = sm + 4096;
    float* Vf = sm + 6144;
    float* Sf = sm + 10240;

    const int tid = threadIdx.x, lane = tid&31, wm = tid>>5;
    const int gid = lane>>2, tig = lane&3;
    const int qt = blockIdx.x, h = blockIdx.y, b = blockIdx.z;
    const int l0 = qt*128;
    const size_t rb = (size_t)b*512;

    const double lgA = -3.4657359027997265, lgB = -6.2383246250395075;
    const float lg2g = (float)(log(1.0 - exp(lgA + (lgB-lgA)*(double)h/3.0)) * 1.4426950408889634);

    {
        const int row = tid>>1, c16 = (tid&1)*16;
        const float* src = QKVG + (rb + l0 + row)*QKN + h*32 + c16;
        float scq = exp2f((float)row * lg2g);
#pragma unroll
        for (int u4=0; u4<4; u4++){
            float4 v = *(const float4*)(src + u4*4);
            float vv[4] = {v.x,v.y,v.z,v.w};
#pragma unroll
            for (int e=0;e<4;e++)
                Qf[a_idx(row, c16+u4*4+e, 4)] = __uint_as_float(tf32r(vv[e]*scq));
        }
    }

    float yacc[8][4];
#pragma unroll
    for (int j=0;j<8;j++)
#pragma unroll
        for (int u=0;u<4;u++) yacc[j][u]=0.f;

    const int srow = tid>>2, sc8 = (tid&3)*8, sc16 = (tid&3)*16;
    const int ntile = 2*qt + 2;

    for (int mt=0; mt<ntile; mt++){
        const int m0 = mt*64;
        const int doff = m0 - l0;
        {
            const float* ks = QKVG + (rb + m0 + srow)*QKN + 128 + h*32 + sc8;
            float sck = exp2f((float)(-doff - srow) * lg2g);
            float4 v0 = *(const float4*)ks, v1 = *(const float4*)(ks+4);
            float kv[8] = {v0.x,v0.y,v0.z,v0.w,v1.x,v1.y,v1.z,v1.w};
#pragma unroll
            for (int u=0;u<8;u++)
                Kf[b_idx(sc8+u, srow, 4)] = __uint_as_float(tf32r(kv[u]*sck));
            const float* vs = QKVG + (rb + m0 + srow)*QKN + 256 + h*64 + sc16;
#pragma unroll
            for (int u=0;u<4;u++){
                float4 v = *(const float4*)(vs + u*4);
                float vv[4] = {v.x,v.y,v.z,v.w};
#pragma unroll
                for (int e=0;e<4;e++)
                    Vf[b_idx(srow, sc16+u*4+e, 8)] = __uint_as_float(tf32r(vv[e]));
            }
        }
        __syncthreads();

        float sacc[8][4];
#pragma unroll
        for (int j=0;j<8;j++)
#pragma unroll
            for (int u=0;u<4;u++) sacc[j][u]=0.f;
#pragma unroll
        for (int kc=0; kc<4; kc++){
            unsigned a[4];
            uint4 t = *(const uint4*)&Qf[(size_t)(wm*4+kc)*128 + lane*4];
            a[0]=t.x; a[1]=t.y; a[2]=t.z; a[3]=t.w;
#pragma unroll
            for (int nj=0;nj<8;nj++){
                uint2 bt = *(const uint2*)&Kf[(size_t)(nj*4+kc)*64 + lane*2];
                unsigned bfr[2] = {bt.x, bt.y};
                mma_tf32(sacc[nj], a, bfr);
            }
        }
        const bool needmask = (doff >= 0);
#pragma unroll
        for (int nj=0;nj<8;nj++){
#pragma unroll
            for (int u=0;u<4;u++){
                int i = wm*16 + gid + (u>>1)*8;
                int j = nj*8 + tig*2 + (u&1);
                float v = sacc[nj][u];
                if (needmask && i < j + doff) v = 0.f;
                Sf[a_idx(i, j, 8)] = __uint_as_float(tf32r(v));
            }
        }
        __syncthreads();

#pragma unroll
        for (int kc=0; kc<8; kc++){
            unsigned a[4];
            uint4 t = *(const uint4*)&Sf[(size_t)(wm*8+kc)*128 + lane*4];
            a[0]=t.x; a[1]=t.y; a[2]=t.z; a[3]=t.w;
#pragma unroll
            for (int nj=0;nj<8;nj++){
                uint2 bt = *(const uint2*)&Vf[(size_t)(nj*8+kc)*64 + lane*2];
                unsigned bfr[2] = {bt.x, bt.y};
                mma_tf32(yacc[nj], a, bfr);
            }
        }
        __syncthreads();
    }

#pragma unroll
    for (int nj=0;nj<8;nj++){
#pragma unroll
        for (int u=0;u<4;u++){
            int i = wm*16 + gid + (u>>1)*8;
            int j = nj*8 + tig*2 + (u&1);
            Sf[i*64 + j] = yacc[nj][u];
        }
    }
    __syncthreads();

#pragma unroll
    for (int half=0; half<2; half++){
        const int r = (tid>>2) + half*64, q = tid&3;
        float sum=0.f, ssq=0.f;
#pragma unroll
        for (int u=0;u<4;u++){
            float4 v = *(const float4*)&Sf[r*64 + q*16 + u*4];
            sum += v.x+v.y+v.z+v.w;
            ssq += v.x*v.x+v.y*v.y+v.z*v.z+v.w*v.w;
        }
        sum += __shfl_xor_sync(~0u,sum,1); ssq += __shfl_xor_sync(~0u,ssq,1);
        sum += __shfl_xor_sync(~0u,sum,2); ssq += __shfl_xor_sync(~0u,ssq,2);
        float mean = sum*(1.f/64.f), var = ssq*(1.f/64.f)-mean*mean;
        float rstd = rsqrtf(var + 1e-5f);
        const float* gs = QKVG + (rb + l0 + r)*QKN + 512 + h*64 + q*16;
        const float* gw = gn_w + h*64 + q*16;
        const float* gb = gn_b + h*64 + q*16;
        const int row_t = (int)(rb + l0 + r);
#pragma unroll
        for (int u=0;u<4;u++){
            float4 yv = *(const float4*)&Sf[r*64 + q*16 + u*4];
            float4 gv = *(const float4*)(gs+u*4);
            float4 wv = *(const float4*)(gw+u*4);
            float4 bv = *(const float4*)(gb+u*4);
            float ov[4];
            ov[0] = ((yv.x-mean)*rstd*wv.x+bv.x)*siluf(gv.x);
            ov[1] = ((yv.y-mean)*rstd*wv.y+bv.y)*siluf(gv.y);
            ov[2] = ((yv.z-mean)*rstd*wv.z+bv.z)*siluf(gv.z);
            ov[3] = ((yv.w-mean)*rstd*wv.w+bv.w)*siluf(gv.w);
#pragma unroll
            for (int e=0;e<4;e++){
                int k = h*64 + q*16 + u*4 + e;
                P[a_idx(row_t, k, 32)] = __uint_as_float(tf32r(ov[e]));
            }
        }
    }
}

// ------------------- decoder + softmax -------------------
__global__ __launch_bounds__(256) void dec_kernel(
    const float* __restrict__ X, const float* __restrict__ w1, const float* __restrict__ b1,
    const float* __restrict__ w2, const float* __restrict__ b2, float* __restrict__ out)
{
    __shared__ float sw1[8192], sw2[1280], sb1[64], sb2[20];
    int tid = threadIdx.x;
    for (int i=tid;i<8192;i+=256) sw1[i]=w1[i];
    for (int i=tid;i<1280;i+=256) sw2[i]=w2[i];
    if (tid<64) sb1[tid]=b1[tid];
    if (tid<20) sb2[tid]=b2[tid];
    __syncthreads();
    int t = blockIdx.x*256 + tid;
    float h[64];
#pragma unroll
    for (int o=0;o<64;o++) h[o]=sb1[o];
    for (int k=0;k<128;k+=4){
        float4 xv = *(const float4*)(X + (size_t)t*128 + k);
#pragma unroll
        for (int o=0;o<64;o++){
            h[o] += xv.x*sw1[(k+0)*64+o] + xv.y*sw1[(k+1)*64+o]
                  + xv.z*sw1[(k+2)*64+o] + xv.w*sw1[(k+3)*64+o];
        }
    }
#pragma unroll
    for (int o=0;o<64;o++) h[o]=geluf(h[o]);
    float lg[20];
#pragma unroll
    for (int o=0;o<20;o++){ float s=sb2[o];
#pragma unroll
        for (int k=0;k<64;k++) s += h[k]*sw2[k*20+o];
        lg[o]=s; }
    float mx = lg[0];
#pragma unroll
    for (int o=1;o<20;o++) mx = fmaxf(mx, lg[o]);
    float sum = 0.f;
#pragma unroll
    for (int o=0;o<20;o++){ lg[o] = expf(lg[o]-mx); sum += lg[o]; }
    float inv = 1.0f/sum;
#pragma unroll
    for (int o=0;o<20;o++) out[(size_t)t*20+o] = lg[o]*inv;
}

// ------------------- launch -------------------
extern "C" void kernel_launch(void* const* d_in, const int* in_sizes, int n_in,
                              void* d_out, int out_size)
{
    const float* x      = (const float*)d_in[0];
    const float* rem_w1 = (const float*)d_in[1];
    const float* rem_b1 = (const float*)d_in[2];
    const float* rem_w2 = (const float*)d_in[3];
    const float* rem_b2 = (const float*)d_in[4];
    const float* rem_w3 = (const float*)d_in[5];
    const float* rem_b3 = (const float*)d_in[6];
    const float* wq     = (const float*)d_in[7];
    const float* wk     = (const float*)d_in[8];
    const float* wv     = (const float*)d_in[9];
    const float* wg     = (const float*)d_in[10];
    const float* wo     = (const float*)d_in[11];
    const float* gn_w   = (const float*)d_in[12];
    const float* gn_b   = (const float*)d_in[13];
    const float* ln1_w  = (const float*)d_in[14];
    const float* ln1_b  = (const float*)d_in[15];
    const float* ln2_w  = (const float*)d_in[16];
    const float* ln2_b  = (const float*)d_in[17];
    const float* ffn_w1 = (const float*)d_in[18];
    const float* ffn_b1 = (const float*)d_in[19];
    const float* ffn_w2 = (const float*)d_in[20];
    const float* ffn_b2 = (const float*)d_in[21];
    const float* dec_w1 = (const float*)d_in[22];
    const float* dec_b1 = (const float*)d_in[23];
    const float* dec_w2 = (const float*)d_in[24];
    const float* dec_b2 = (const float*)d_in[25];
    float* out = (float*)d_out;

    float *pX,*pY1,*pQK,*pXn,*pP,*pHf,*pWq,*pWo,*pW1,*pW2;
    cudaGetSymbolAddress((void**)&pX,  g_X);
    cudaGetSymbolAddress((void**)&pY1, g_Y1);
    cudaGetSymbolAddress((void**)&pQK, g_QK);
    cudaGetSymbolAddress((void**)&pXn, g_Xn);
    cudaGetSymbolAddress((void**)&pP,  g_P);
    cudaGetSymbolAddress((void**)&pHf, g_Hf);
    cudaGetSymbolAddress((void**)&pWq, g_Wq);
    cudaGetSymbolAddress((void**)&pWo, g_Wo);
    cudaGetSymbolAddress((void**)&pW1, g_W1);
    cudaGetSymbolAddress((void**)&pW2, g_W2);

    cudaFuncSetAttribute(retention_kernel,
        cudaFuncAttributeMaxDynamicSharedMemorySize, RET_SMEM);

    xpos_table_kernel<<<32, 256>>>();
    wfrag_all_kernel<<<(4*196608)/256, 256>>>(wq, wk, wv, wg, wo, ffn_w1, ffn_w2);
    rem_kernel<<<TOKENS/256, 256>>>(x, rem_w1, rem_b1, rem_w2, rem_b2, rem_w3, rem_b3, pX);
    ln_frag_kernel<<<TOKENS/8, 256>>>(pX, ln1_w, ln1_b, pXn);   // layer 0 ln1

    for (int l = 0; l < 4; l++){
        gemm_f<2><<<dim3(QKN/64, TOKENS/128), 256>>>(
            pXn, pWq + (size_t)l*HID*QKN, nullptr, nullptr, pQK, nullptr, QKN, HID);
        retention_kernel<<<dim3(4, 4, 64), 256, RET_SMEM>>>(pQK, gn_w + l*VD, gn_b + l*VD, pP);
        // wo GEMM + residual(X) + LN2 -> (Y1, Xn)
        gemm_ln<<<TOKENS/128, 256>>>(
            pP, pWo + (size_t)l*VD*HID, nullptr, pX,
            ln2_w + l*128, ln2_b + l*128, pY1, pXn, VD);
        gemm_f<1><<<dim3(FFND/64, TOKENS/128), 256>>>(
            pXn, pW1 + (size_t)l*HID*FFND, ffn_b1 + l*FFND, nullptr, nullptr, pHf, FFND, HID);
        if (l < 3){
            // ffn2 + bias + residual(Y1) + LN1[l+1] -> (X, Xn)
            gemm_ln<<<TOKENS/128, 256>>>(
                pHf, pW2 + (size_t)l*FFND*HID, ffn_b2 + l*128, pY1,
                ln1_w + (l+1)*128, ln1_b + (l+1)*128, pX, pXn, FFND);
        } else {
            gemm_f<3><<<dim3(HID/64, TOKENS/128), 256>>>(
                pHf, pW2 + (size_t)l*FFND*HID, ffn_b2 + l*HID, pY1, pX, nullptr, HID, FFND);
        }
    }
    dec_kernel<<<TOKENS/256, 256>>>(pX, dec_w1, dec_b1, dec_w2, dec_b2, out);
}

// round 10
// speedup vs baseline: 1.2138x; 1.2138x over previous
#include <cuda_runtime.h>
#include <math.h>
#include <stdint.h>

#define TOKENS 32768
#define LSEQ   512
#define HID    128
#define VD     256
#define FFND   256
#define QKN    768   // 128 Q | 128 K | 256 V | 256 G

// fp32 row-major buffers
__device__ float g_X [TOKENS * HID];
__device__ float g_Y1[TOKENS * HID];
__device__ float g_G [TOKENS * VD];              // gate stream (fp32)
// fragment-major (tf32 bits) operand buffers
__device__ float g_Xn[TOKENS * HID];
__device__ float g_P [TOKENS * VD];
__device__ float g_Hf[TOKENS * FFND];
__device__ float g_Qf[64*4*16384];               // per (b,h): A-frags [512 x 32], gamma^i, xpos
__device__ float g_Kf[64*4*16384];               // per (b,h): B-frags k=dim32, n=seq512, gamma^-j
__device__ float g_Vf[(size_t)64*4*32768];       // per (b,h): B-frags k=seq512, n=v64
__device__ float g_Wq[4 * HID * QKN];
__device__ float g_Wo[4 * VD * HID];
__device__ float g_W1[4 * HID * FFND];
__device__ float g_W2[4 * FFND * HID];
__device__ float g_qc[LSEQ*16], g_qs[LSEQ*16], g_kc[LSEQ*16], g_ks[LSEQ*16];
__device__ float g_lg2g[4];

__device__ __forceinline__ float geluf(float v){ return 0.5f*v*(1.0f+erff(v*0.70710678f)); }
__device__ __forceinline__ float siluf(float v){ return v/(1.0f+expf(-v)); }
__device__ __forceinline__ unsigned tf32r(float x){
    unsigned r; asm("cvt.rna.tf32.f32 %0, %1;" : "=r"(r) : "f"(x)); return r;
}
__device__ __forceinline__ void mma_tf32(float* d, const unsigned* a, const unsigned* b){
    asm volatile("mma.sync.aligned.m16n8k8.row.col.f32.tf32.tf32.f32 "
        "{%0,%1,%2,%3},{%4,%5,%6,%7},{%8,%9},{%0,%1,%2,%3};"
        : "+f"(d[0]),"+f"(d[1]),"+f"(d[2]),"+f"(d[3])
        : "r"(a[0]),"r"(a[1]),"r"(a[2]),"r"(a[3]), "r"(b[0]),"r"(b[1]));
}

__device__ __forceinline__ size_t a_idx(int row, int k, int K8){
    return ((size_t)((row>>4)*K8 + (k>>3)))*128 + (size_t)((row&7)*16 + (k&3)*4
           + ((row>>3)&1) + (((k>>2)&1)<<1));
}
__device__ __forceinline__ size_t b_idx(int k, int n, int K8){
    return ((size_t)((n>>3)*K8 + (k>>3)))*64 + (size_t)((n&7)*8 + (k&3)*2 + ((k>>2)&1));
}

// ------------------- xpos tables + per-head log2(gamma) -------------------
__global__ void xpos_table_kernel(){
    int idx = blockIdx.x*256 + threadIdx.x;
    if (idx < 4){
        double lgA=-3.4657359027997265, lgB=-6.2383246250395075;
        g_lg2g[idx] = (float)(log(1.0 - exp(lgA + (lgB-lgA)*(double)idx/3.0)) * 1.4426950408889634);
    }
    if (idx >= LSEQ*16) return;
    int l = idx >> 4, j = idx & 15;
    float base = ((float)j + 12.8f) / 44.8f;
    float sc   = powf(base, (float)l / 512.0f);
    float ang  = (float)l * powf(10000.0f, -(float)j/16.0f);
    float s, c; sincosf(ang, &s, &c);
    g_qc[idx]=c*sc; g_qs[idx]=s*sc; g_kc[idx]=c/sc; g_ks[idx]=s/sc;
}

// ------------------- ALL weights -> B-fragment layout (tf32), one launch -------------------
__global__ void wfrag_all_kernel(
    const float* __restrict__ wq, const float* __restrict__ wk,
    const float* __restrict__ wv, const float* __restrict__ wg,
    const float* __restrict__ wo, const float* __restrict__ w1,
    const float* __restrict__ w2)
{
    int idx = blockIdx.x*256 + threadIdx.x;
    int l = idx / 196608, r = idx % 196608;
    if (r < 98304){
        int k = r / QKN, n = r % QKN;
        float v;
        if (n < 128)      v = wq[(((size_t)l*4 + (n>>5))*HID + k)*32 + (n&31)];
        else if (n < 256) { int c=n-128; v = wk[(((size_t)l*4 + (c>>5))*HID + k)*32 + (c&31)]; }
        else if (n < 512) { int c=n-256; v = wv[(((size_t)l*4 + (c>>6))*HID + k)*64 + (c&63)]; }
        else              v = wg[((size_t)l*HID + k)*VD + (n-512)];
        g_Wq[(size_t)l*HID*QKN + b_idx(k, n, 16)] = __uint_as_float(tf32r(v));
    } else {
        int r2 = r - 98304;
        int m = r2 >> 15, e = r2 & 32767;
        if (m == 0){
            int k = e >> 7, n = e & 127;
            g_Wo[(size_t)l*VD*HID + b_idx(k, n, 32)] =
                __uint_as_float(tf32r(wo[(size_t)l*VD*HID + (size_t)k*HID + n]));
        } else if (m == 1){
            int k = e >> 8, n = e & 255;
            g_W1[(size_t)l*HID*FFND + b_idx(k, n, 16)] =
                __uint_as_float(tf32r(w1[(size_t)l*HID*FFND + (size_t)k*FFND + n]));
        } else {
            int k = e >> 7, n = e & 127;
            g_W2[(size_t)l*FFND*HID + b_idx(k, n, 32)] =
                __uint_as_float(tf32r(w2[(size_t)l*FFND*HID + (size_t)k*HID + n]));
        }
    }
}

// ------------------- input MLP -------------------
__global__ __launch_bounds__(256) void rem_kernel(
    const float* __restrict__ x,
    const float* __restrict__ w1, const float* __restrict__ b1,
    const float* __restrict__ w2, const float* __restrict__ b2,
    const float* __restrict__ w3, const float* __restrict__ b3,
    float* __restrict__ X)
{
    __shared__ float sw1[160], sb1[32], sw2[2048], sb2[64], sw3[8192], sb3[128];
    int tid = threadIdx.x;
    for (int i=tid;i<160; i+=256) sw1[i]=w1[i];
    for (int i=tid;i<2048;i+=256) sw2[i]=w2[i];
    for (int i=tid;i<8192;i+=256) sw3[i]=w3[i];
    if (tid<32)  sb1[tid]=b1[tid];
    if (tid<64)  sb2[tid]=b2[tid];
    if (tid<128) sb3[tid]=b3[tid];
    __syncthreads();
    int t = blockIdx.x*256 + tid;
    float xin[5];
#pragma unroll
    for (int k=0;k<5;k++) xin[k] = x[(size_t)t*5+k];
    float h1[32];
#pragma unroll
    for (int o=0;o<32;o++){ float s=sb1[o];
#pragma unroll
        for (int k=0;k<5;k++) s += xin[k]*sw1[k*32+o];
        h1[o]=geluf(s); }
    float h2[64];
#pragma unroll
    for (int o=0;o<64;o++){ float s=sb2[o];
#pragma unroll
        for (int k=0;k<32;k++) s += h1[k]*sw2[k*64+o];
        h2[o]=geluf(s); }
    for (int o=0;o<128;o+=4){
        float v0=sb3[o],v1=sb3[o+1],v2=sb3[o+2],v3=sb3[o+3];
#pragma unroll
        for (int k=0;k<64;k++){ float hk=h2[k];
            v0+=hk*sw3[k*128+o]; v1+=hk*sw3[k*128+o+1];
            v2+=hk*sw3[k*128+o+2]; v3+=hk*sw3[k*128+o+3]; }
        *(float4*)(X+(size_t)t*128+o) = make_float4(geluf(v0),geluf(v1),geluf(v2),geluf(v3));
    }
}

// ------------------- LayerNorm(128) -> A-fragment layout -------------------
__global__ __launch_bounds__(256) void ln_frag_kernel(
    const float* __restrict__ X, const float* __restrict__ w,
    const float* __restrict__ b, float* __restrict__ out)
{
    int g = blockIdx.x*256 + threadIdx.x;
    int row = g>>5, lane = g&31;
    float4 v = *(const float4*)(X + (size_t)row*128 + lane*4);
    float s = v.x+v.y+v.z+v.w;
    float s2 = v.x*v.x+v.y*v.y+v.z*v.z+v.w*v.w;
#pragma unroll
    for (int o=16;o;o>>=1){ s += __shfl_xor_sync(~0u,s,o); s2 += __shfl_xor_sync(~0u,s2,o); }
    float mean = s*(1.f/128.f), var = s2*(1.f/128.f)-mean*mean;
    float rstd = rsqrtf(var + 1e-5f);
    float4 wv = *(const float4*)(w+lane*4), bv = *(const float4*)(b+lane*4);
    float rv[4];
    rv[0]=(v.x-mean)*rstd*wv.x+bv.x; rv[1]=(v.y-mean)*rstd*wv.y+bv.y;
    rv[2]=(v.z-mean)*rstd*wv.z+bv.z; rv[3]=(v.w-mean)*rstd*wv.w+bv.w;
#pragma unroll
    for (int j=0;j<4;j++){
        int k = lane*4 + j;
        out[a_idx(row, k, 16)] = __uint_as_float(tf32r(rv[j]));
    }
}

// ------------------- fragment-fed tf32 GEMM (128x64 tile). OP: 1 gelu->Afrag, 3 [bias]+residual ----
template<int OP>
__global__ __launch_bounds__(256) void gemm_f(
    const float* __restrict__ Af, const float* __restrict__ Bf,
    const float* __restrict__ bias, const float* __restrict__ R,
    float* __restrict__ Cf, float* __restrict__ Ca, int N, int K)
{
    const int tid = threadIdx.x, lane = tid & 31, wid = tid >> 5;
    const int wm = wid & 3, wn = wid >> 2;
    const int m0 = blockIdx.y*128, n0 = blockIdx.x*64;
    const int K8 = K >> 3;

    float acc[2][4][4];
#pragma unroll
    for (int i=0;i<2;i++)
#pragma unroll
        for (int j=0;j<4;j++)
#pragma unroll
            for (int u=0;u<4;u++) acc[i][j][u]=0.f;

    const float* Ab = Af + ((size_t)((m0>>4) + wm*2))*K8*128 + lane*4;
    const float* Bb = Bf + ((size_t)((n0>>3) + wn*4))*K8*64  + lane*2;

#pragma unroll 2
    for (int kc = 0; kc < K8; kc++){
        unsigned a[2][4], b[4][2];
#pragma unroll
        for (int mi=0;mi<2;mi++){
            uint4 t = *(const uint4*)(Ab + ((size_t)mi*K8 + kc)*128);
            a[mi][0]=t.x; a[mi][1]=t.y; a[mi][2]=t.z; a[mi][3]=t.w;
        }
#pragma unroll
        for (int ni=0;ni<4;ni++){
            uint2 t = *(const uint2*)(Bb + ((size_t)ni*K8 + kc)*64);
            b[ni][0]=t.x; b[ni][1]=t.y;
        }
#pragma unroll
        for (int mi=0;mi<2;mi++)
#pragma unroll
            for (int ni=0;ni<4;ni++)
                mma_tf32(acc[mi][ni], a[mi], b[ni]);
    }

    const int gid = lane>>2, tig = lane&3;
#pragma unroll
    for (int mi=0;mi<2;mi++)
#pragma unroll
        for (int ni=0;ni<4;ni++){
            int col = n0 + wn*32 + ni*8 + tig*2;
            float bb0=0.f, bb1=0.f;
            if (bias){ float2 bv = *(const float2*)(bias+col); bb0=bv.x; bb1=bv.y; }
#pragma unroll
            for (int hh=0; hh<2; hh++){
                int row = m0 + wm*32 + mi*16 + gid + hh*8;
                float v0 = acc[mi][ni][hh*2+0] + bb0;
                float v1 = acc[mi][ni][hh*2+1] + bb1;
                if (OP==1){
                    v0 = geluf(v0); v1 = geluf(v1);
                    int K8o = N >> 3;
                    Ca[a_idx(row, col,   K8o)] = __uint_as_float(tf32r(v0));
                    Ca[a_idx(row, col+1, K8o)] = __uint_as_float(tf32r(v1));
                } else {
                    float2 rv = *(const float2*)(R + (size_t)row*N + col);
                    v0+=rv.x; v1+=rv.y;
                    *(float2*)(Cf + (size_t)row*N + col) = make_float2(v0,v1);
                }
            }
        }
}

// ------------------- QKVG GEMM: N=768, K=128; epilogue -> per-head frag buffers -------------------
__global__ __launch_bounds__(256) void gemm_qkvg(
    const float* __restrict__ Af, const float* __restrict__ Bf)
{
    const int tid = threadIdx.x, lane = tid & 31, wid = tid >> 5;
    const int wm = wid & 3, wn = wid >> 2;
    const int m0 = blockIdx.y*128, n0 = blockIdx.x*64;
    const int K8 = 16;

    float acc[2][4][4];
#pragma unroll
    for (int i=0;i<2;i++)
#pragma unroll
        for (int j=0;j<4;j++)
#pragma unroll
            for (int u=0;u<4;u++) acc[i][j][u]=0.f;

    const float* Ab = Af + ((size_t)((m0>>4) + wm*2))*K8*128 + lane*4;
    const float* Bb = Bf + ((size_t)((n0>>3) + wn*4))*K8*64  + lane*2;

#pragma unroll 2
    for (int kc = 0; kc < K8; kc++){
        unsigned a[2][4], b[4][2];
#pragma unroll
        for (int mi=0;mi<2;mi++){
            uint4 t = *(const uint4*)(Ab + ((size_t)mi*K8 + kc)*128);
            a[mi][0]=t.x; a[mi][1]=t.y; a[mi][2]=t.z; a[mi][3]=t.w;
        }
#pragma unroll
        for (int ni=0;ni<4;ni++){
            uint2 t = *(const uint2*)(Bb + ((size_t)ni*K8 + kc)*64);
            b[ni][0]=t.x; b[ni][1]=t.y;
        }
#pragma unroll
        for (int mi=0;mi<2;mi++)
#pragma unroll
            for (int ni=0;ni<4;ni++)
                mma_tf32(acc[mi][ni], a[mi], b[ni]);
    }

    const int gid = lane>>2, tig = lane&3;
#pragma unroll
    for (int mi=0;mi<2;mi++)
#pragma unroll
        for (int ni=0;ni<4;ni++){
            int col = n0 + wn*32 + ni*8 + tig*2;
#pragma unroll
            for (int hh=0; hh<2; hh++){
                int t = m0 + wm*32 + mi*16 + gid + hh*8;
                int bb = t >> 9, ii = t & 511;
                float v0 = acc[mi][ni][hh*2+0];
                float v1 = acc[mi][ni][hh*2+1];
                if (col < 256){
                    const float* ct = (col<128)? g_qc : g_kc;
                    const float* st = (col<128)? g_qs : g_ks;
                    int j = (col&31)>>1;
                    float c0=ct[ii*16+j], s0=st[ii*16+j];
                    float t0 = v0*c0 - v1*s0, t1 = v1*c0 + v0*s0;
                    if (col < 128){
                        int h = col>>5, d = col&31;
                        float sc = exp2f((float)ii * g_lg2g[h]);
                        float* dst = g_Qf + ((size_t)(bb*4+h))*16384;
                        dst[a_idx(ii, d,   4)] = __uint_as_float(tf32r(t0*sc));
                        dst[a_idx(ii, d+1, 4)] = __uint_as_float(tf32r(t1*sc));
                    } else {
                        int h = (col-128)>>5, d = (col-128)&31;
                        float sc = exp2f(-(float)ii * g_lg2g[h]);
                        float* dst = g_Kf + ((size_t)(bb*4+h))*16384;
                        dst[b_idx(d,   ii, 4)] = __uint_as_float(tf32r(t0*sc));
                        dst[b_idx(d+1, ii, 4)] = __uint_as_float(tf32r(t1*sc));
                    }
                } else if (col < 512){
                    int h = (col-256)>>6, v = (col-256)&63;
                    float* dst = g_Vf + ((size_t)(bb*4+h))*32768;
                    dst[b_idx(ii, v,   64)] = __uint_as_float(tf32r(v0));
                    dst[b_idx(ii, v+1, 64)] = __uint_as_float(tf32r(v1));
                } else {
                    *(float2*)(g_G + (size_t)t*VD + (col-512)) = make_float2(v0, v1);
                }
            }
        }
}

// ------------------- Retention: frag-fed, Q in regs, coalesced K/V staging -------------------
// dyn smem (floats): Ks[2048] @0, Vs[4096] @2048, Sf[8192] @6144 -> 14336 (56KB)
#define RET_SMEM (14336*4)
__global__ __launch_bounds__(256) void retention_kernel(
    const float* __restrict__ Qf, const float* __restrict__ Kf,
    const float* __restrict__ Vf, const float* __restrict__ G,
    const float* __restrict__ gn_w, const float* __restrict__ gn_b,
    float* __restrict__ P)
{
    extern __shared__ float sm[];
    float* Ks = sm;
    float* Vs = sm + 2048;
    float* Sf = sm + 6144;

    const int tid = threadIdx.x, lane = tid&31, wm = tid>>5;
    const int gid = lane>>2, tig = lane&3;
    const int qt = blockIdx.x, h = blockIdx.y, b = blockIdx.z;
    const int l0 = qt*128;
    const size_t rb = (size_t)b*512;
    const size_t bh = (size_t)(b*4 + h);
    const float* Qg = Qf + bh*16384;
    const float* Kg = Kf + bh*16384;
    const float4* Vg = (const float4*)(Vf + bh*32768);

    // Q fragments -> registers (reused across all key tiles)
    unsigned qf[4][4];
#pragma unroll
    for (int kc=0; kc<4; kc++){
        uint4 t = *(const uint4*)(Qg + ((size_t)(((l0>>4)+wm)*4+kc))*128 + lane*4);
        qf[kc][0]=t.x; qf[kc][1]=t.y; qf[kc][2]=t.z; qf[kc][3]=t.w;
    }

    float yacc[8][4];
#pragma unroll
    for (int j=0;j<8;j++)
#pragma unroll
        for (int u=0;u<4;u++) yacc[j][u]=0.f;

    const int ntile = 2*qt + 2;

    for (int mt=0; mt<ntile; mt++){
        const int doff = mt*64 - l0;
        // stage K (512 float4) + V (1024 float4), coalesced
        {
            const float4* ksrc = (const float4*)(Kg + mt*2048);
            float4* kdst = (float4*)Ks;
#pragma unroll
            for (int i4 = tid; i4 < 512; i4 += 256) kdst[i4] = ksrc[i4];
            float4* vdst = (float4*)Vs;
#pragma unroll
            for (int i4 = tid; i4 < 1024; i4 += 256){
                int vg = i4 >> 7, rem = i4 & 127;
                vdst[vg*128 + rem] = Vg[(vg*64 + mt*8)*16 + rem];
            }
        }
        __syncthreads();

        // S = Q K^T (decay pre-baked)
        float sacc[8][4];
#pragma unroll
        for (int j=0;j<8;j++)
#pragma unroll
            for (int u=0;u<4;u++) sacc[j][u]=0.f;
#pragma unroll
        for (int kc=0; kc<4; kc++){
#pragma unroll
            for (int nj=0;nj<8;nj++){
                uint2 bt = *(const uint2*)&Ks[(size_t)(nj*4+kc)*64 + lane*2];
                unsigned bfr[2] = {bt.x, bt.y};
                mma_tf32(sacc[nj], qf[kc], bfr);
            }
        }
        const bool needmask = (doff >= 0);
#pragma unroll
        for (int nj=0;nj<8;nj++){
#pragma unroll
            for (int u=0;u<4;u++){
                int i = wm*16 + gid + (u>>1)*8;
                int j = nj*8 + tig*2 + (u&1);
                float v = sacc[nj][u];
                if (needmask && i < j + doff) v = 0.f;
                Sf[a_idx(i, j, 8)] = __uint_as_float(tf32r(v));
            }
        }
        __syncthreads();

        // Y += S @ V
#pragma unroll
        for (int kc=0; kc<8; kc++){
            unsigned a[4];
            uint4 t = *(const uint4*)&Sf[(size_t)(wm*8+kc)*128 + lane*4];
            a[0]=t.x; a[1]=t.y; a[2]=t.z; a[3]=t.w;
#pragma unroll
            for (int nj=0;nj<8;nj++){
                uint2 bt = *(const uint2*)&Vs[(size_t)(nj*8+kc)*64 + lane*2];
                unsigned bfr[2] = {bt.x, bt.y};
                mma_tf32(yacc[nj], a, bfr);
            }
        }
        __syncthreads();
    }

    // dump Y row-major into Sf for group-norm
#pragma unroll
    for (int nj=0;nj<8;nj++){
#pragma unroll
        for (int u=0;u<4;u++){
            int i = wm*16 + gid + (u>>1)*8;
            int j = nj*8 + tig*2 + (u&1);
            Sf[i*64 + j] = yacc[nj][u];
        }
    }
    __syncthreads();

#pragma unroll
    for (int half=0; half<2; half++){
        const int r = (tid>>2) + half*64, q = tid&3;
        float sum=0.f, ssq=0.f;
#pragma unroll
        for (int u=0;u<4;u++){
            float4 v = *(const float4*)&Sf[r*64 + q*16 + u*4];
            sum += v.x+v.y+v.z+v.w;
            ssq += v.x*v.x+v.y*v.y+v.z*v.z+v.w*v.w;
        }
        sum += __shfl_xor_sync(~0u,sum,1); ssq += __shfl_xor_sync(~0u,ssq,1);
        sum += __shfl_xor_sync(~0u,sum,2); ssq += __shfl_xor_sync(~0u,ssq,2);
        float mean = sum*(1.f/64.f), var = ssq*(1.f/64.f)-mean*mean;
        float rstd = rsqrtf(var + 1e-5f);
        const float* gs = G + (rb + l0 + r)*VD + h*64 + q*16;
        const float* gw = gn_w + h*64 + q*16;
        const float* gb = gn_b + h*64 + q*16;
        const int row_t = (int)(rb + l0 + r);
#pragma unroll
        for (int u=0;u<4;u++){
            float4 yv = *(const float4*)&Sf[r*64 + q*16 + u*4];
            float4 gv = *(const float4*)(gs+u*4);
            float4 wv = *(const float4*)(gw+u*4);
            float4 bv = *(const float4*)(gb+u*4);
            float ov[4];
            ov[0] = ((yv.x-mean)*rstd*wv.x+bv.x)*siluf(gv.x);
            ov[1] = ((yv.y-mean)*rstd*wv.y+bv.y)*siluf(gv.y);
            ov[2] = ((yv.z-mean)*rstd*wv.z+bv.z)*siluf(gv.z);
            ov[3] = ((yv.w-mean)*rstd*wv.w+bv.w)*siluf(gv.w);
#pragma unroll
            for (int e=0;e<4;e++){
                int k = h*64 + q*16 + u*4 + e;
                P[a_idx(row_t, k, 32)] = __uint_as_float(tf32r(ov[e]));
            }
        }
    }
}

// ------------------- decoder + softmax -------------------
__global__ __launch_bounds__(256) void dec_kernel(
    const float* __restrict__ X, const float* __restrict__ w1, const float* __restrict__ b1,
    const float* __restrict__ w2, const float* __restrict__ b2, float* __restrict__ out)
{
    __shared__ float sw1[8192], sw2[1280], sb1[64], sb2[20];
    int tid = threadIdx.x;
    for (int i=tid;i<8192;i+=256) sw1[i]=w1[i];
    for (int i=tid;i<1280;i+=256) sw2[i]=w2[i];
    if (tid<64) sb1[tid]=b1[tid];
    if (tid<20) sb2[tid]=b2[tid];
    __syncthreads();
    int t = blockIdx.x*256 + tid;
    float h[64];
#pragma unroll
    for (int o=0;o<64;o++) h[o]=sb1[o];
    for (int k=0;k<128;k+=4){
        float4 xv = *(const float4*)(X + (size_t)t*128 + k);
#pragma unroll
        for (int o=0;o<64;o++){
            h[o] += xv.x*sw1[(k+0)*64+o] + xv.y*sw1[(k+1)*64+o]
                  + xv.z*sw1[(k+2)*64+o] + xv.w*sw1[(k+3)*64+o];
        }
    }
#pragma unroll
    for (int o=0;o<64;o++) h[o]=geluf(h[o]);
    float lg[20];
#pragma unroll
    for (int o=0;o<20;o++){ float s=sb2[o];
#pragma unroll
        for (int k=0;k<64;k++) s += h[k]*sw2[k*20+o];
        lg[o]=s; }
    float mx = lg[0];
#pragma unroll
    for (int o=1;o<20;o++) mx = fmaxf(mx, lg[o]);
    float sum = 0.f;
#pragma unroll
    for (int o=0;o<20;o++){ lg[o] = expf(lg[o]-mx); sum += lg[o]; }
    float inv = 1.0f/sum;
#pragma unroll
    for (int o=0;o<20;o++) out[(size_t)t*20+o] = lg[o]*inv;
}

// ------------------- launch -------------------
extern "C" void kernel_launch(void* const* d_in, const int* in_sizes, int n_in,
                              void* d_out, int out_size)
{
    const float* x      = (const float*)d_in[0];
    const float* rem_w1 = (const float*)d_in[1];
    const float* rem_b1 = (const float*)d_in[2];
    const float* rem_w2 = (const float*)d_in[3];
    const float* rem_b2 = (const float*)d_in[4];
    const float* rem_w3 = (const float*)d_in[5];
    const float* rem_b3 = (const float*)d_in[6];
    const float* wq     = (const float*)d_in[7];
    const float* wk     = (const float*)d_in[8];
    const float* wv     = (const float*)d_in[9];
    const float* wg     = (const float*)d_in[10];
    const float* wo     = (const float*)d_in[11];
    const float* gn_w   = (const float*)d_in[12];
    const float* gn_b   = (const float*)d_in[13];
    const float* ln1_w  = (const float*)d_in[14];
    const float* ln1_b  = (const float*)d_in[15];
    const float* ln2_w  = (const float*)d_in[16];
    const float* ln2_b  = (const float*)d_in[17];
    const float* ffn_w1 = (const float*)d_in[18];
    const float* ffn_b1 = (const float*)d_in[19];
    const float* ffn_w2 = (const float*)d_in[20];
    const float* ffn_b2 = (const float*)d_in[21];
    const float* dec_w1 = (const float*)d_in[22];
    const float* dec_b1 = (const float*)d_in[23];
    const float* dec_w2 = (const float*)d_in[24];
    const float* dec_b2 = (const float*)d_in[25];
    float* out = (float*)d_out;

    float *pX,*pY1,*pXn,*pP,*pHf,*pWq,*pWo,*pW1,*pW2,*pQf,*pKf,*pVf,*pG;
    cudaGetSymbolAddress((void**)&pX,  g_X);
    cudaGetSymbolAddress((void**)&pY1, g_Y1);
    cudaGetSymbolAddress((void**)&pXn, g_Xn);
    cudaGetSymbolAddress((void**)&pP,  g_P);
    cudaGetSymbolAddress((void**)&pHf, g_Hf);
    cudaGetSymbolAddress((void**)&pWq, g_Wq);
    cudaGetSymbolAddress((void**)&pWo, g_Wo);
    cudaGetSymbolAddress((void**)&pW1, g_W1);
    cudaGetSymbolAddress((void**)&pW2, g_W2);
    cudaGetSymbolAddress((void**)&pQf, g_Qf);
    cudaGetSymbolAddress((void**)&pKf, g_Kf);
    cudaGetSymbolAddress((void**)&pVf, g_Vf);
    cudaGetSymbolAddress((void**)&pG,  g_G);

    cudaFuncSetAttribute(retention_kernel,
        cudaFuncAttributeMaxDynamicSharedMemorySize, RET_SMEM);

    xpos_table_kernel<<<32, 256>>>();
    wfrag_all_kernel<<<(4*196608)/256, 256>>>(wq, wk, wv, wg, wo, ffn_w1, ffn_w2);
    rem_kernel<<<TOKENS/256, 256>>>(x, rem_w1, rem_b1, rem_w2, rem_b2, rem_w3, rem_b3, pX);

    for (int l = 0; l < 4; l++){
        ln_frag_kernel<<<TOKENS/8, 256>>>(pX, ln1_w + l*128, ln1_b + l*128, pXn);
        gemm_qkvg<<<dim3(QKN/64, TOKENS/128), 256>>>(pXn, pWq + (size_t)l*HID*QKN);
        retention_kernel<<<dim3(4, 4, 64), 256, RET_SMEM>>>(
            pQf, pKf, pVf, pG, gn_w + l*VD, gn_b + l*VD, pP);
        gemm_f<3><<<dim3(HID/64, TOKENS/128), 256>>>(
            pP, pWo + (size_t)l*VD*HID, nullptr, pX, pY1, nullptr, HID, VD);
        ln_frag_kernel<<<TOKENS/8, 256>>>(pY1, ln2_w + l*128, ln2_b + l*128, pXn);
        gemm_f<1><<<dim3(FFND/64, TOKENS/128), 256>>>(
            pXn, pW1 + (size_t)l*HID*FFND, ffn_b1 + l*FFND, nullptr, nullptr, pHf, FFND, HID);
        gemm_f<3><<<dim3(HID/64, TOKENS/128), 256>>>(
            pHf, pW2 + (size_t)l*FFND*HID, ffn_b2 + l*HID, pY1, pX, nullptr, HID, FFND);
    }
    dec_kernel<<<TOKENS/256, 256>>>(pX, dec_w1, dec_b1, dec_w2, dec_b2, out);
}

// round 11
// speedup vs baseline: 1.9017x; 1.5667x over previous
#include <cuda_runtime.h>
#include <cuda_bf16.h>
#include <math.h>
#include <stdint.h>

#define TOKENS 32768
#define LSEQ   512
#define HID    128
#define VD     256
#define FFND   256
#define QKN    768   // 128 Q | 128 K | 256 V | 256 G

typedef unsigned short u16;

// fp32 row-major buffers
__device__ float g_X [TOKENS * HID];
__device__ float g_Y1[TOKENS * HID];
__device__ float g_G [TOKENS * VD];
// bf16 fragment-major operand buffers
__device__ u16 g_Xn[TOKENS * HID];
__device__ u16 g_P [TOKENS * VD];
__device__ u16 g_Hf[TOKENS * FFND];
__device__ u16 g_Qf[64*4*16384];                 // per (b,h): A-frags [512 x 32] (Kt=2)
__device__ u16 g_Kf[64*4*16384];                 // per (b,h): B-frags k=dim32,n=seq512 (Kt=2)
__device__ u16 g_Vf[(size_t)64*4*32768];         // per (b,h): B-frags k=seq512,n=64 (Kt=32)
__device__ u16 g_Wq[4 * HID * QKN];
__device__ u16 g_Wo[4 * VD * HID];
__device__ u16 g_W1[4 * HID * FFND];
__device__ u16 g_W2[4 * FFND * HID];
__device__ float g_qc[LSEQ*16], g_qs[LSEQ*16], g_kc[LSEQ*16], g_ks[LSEQ*16];
__device__ float g_lg2g[4];

__device__ __forceinline__ float geluf(float v){ return 0.5f*v*(1.0f+erff(v*0.70710678f)); }
__device__ __forceinline__ float siluf(float v){ return v/(1.0f+expf(-v)); }
__device__ __forceinline__ unsigned bf2(float a, float b){
    __nv_bfloat162 t = __floats2bfloat162_rn(a, b);
    return *(unsigned*)&t;
}
__device__ __forceinline__ u16 bf1(float a){
    __nv_bfloat16 t = __float2bfloat16_rn(a);
    return *(u16*)&t;
}
__device__ __forceinline__ void mma_bf16(float* d, const unsigned* a, const unsigned* b){
    asm volatile("mma.sync.aligned.m16n8k16.row.col.f32.bf16.bf16.f32 "
        "{%0,%1,%2,%3},{%4,%5,%6,%7},{%8,%9},{%0,%1,%2,%3};"
        : "+f"(d[0]),"+f"(d[1]),"+f"(d[2]),"+f"(d[3])
        : "r"(a[0]),"r"(a[1]),"r"(a[2]),"r"(a[3]), "r"(b[0]),"r"(b[1]));
}

// A-fragment ushort index, m16n8k16 bf16. Kt = K/16.
__device__ __forceinline__ size_t a16(int row, int k, int Kt){
    return ((size_t)((row>>4)*Kt + (k>>4)))*256 +
           (size_t)(((row&7)*4 + ((k&7)>>1))*8 + (((row>>3)&1) + (((k>>3)&1)<<1))*2 + (k&1));
}
// B-fragment ushort index
__device__ __forceinline__ size_t b16(int k, int n, int Kt){
    return ((size_t)((n>>3)*Kt + (k>>4)))*128 +
           (size_t)(((n&7)*4 + ((k&7)>>1))*4 + (((k>>3)&1)<<1) + (k&1));
}

// ------------------- xpos tables + per-head log2(gamma) -------------------
__global__ void xpos_table_kernel(){
    int idx = blockIdx.x*256 + threadIdx.x;
    if (idx < 4){
        double lgA=-3.4657359027997265, lgB=-6.2383246250395075;
        g_lg2g[idx] = (float)(log(1.0 - exp(lgA + (lgB-lgA)*(double)idx/3.0)) * 1.4426950408889634);
    }
    if (idx >= LSEQ*16) return;
    int l = idx >> 4, j = idx & 15;
    float base = ((float)j + 12.8f) / 44.8f;
    float sc   = powf(base, (float)l / 512.0f);
    float ang  = (float)l * powf(10000.0f, -(float)j/16.0f);
    float s, c; sincosf(ang, &s, &c);
    g_qc[idx]=c*sc; g_qs[idx]=s*sc; g_kc[idx]=c/sc; g_ks[idx]=s/sc;
}

// ------------------- ALL weights -> bf16 B-fragment layout, one launch -------------------
__global__ void wfrag_all_kernel(
    const float* __restrict__ wq, const float* __restrict__ wk,
    const float* __restrict__ wv, const float* __restrict__ wg,
    const float* __restrict__ wo, const float* __restrict__ w1,
    const float* __restrict__ w2)
{
    int idx = blockIdx.x*256 + threadIdx.x;
    int l = idx / 196608, r = idx % 196608;
    if (r < 98304){
        int k = r / QKN, n = r % QKN;
        float v;
        if (n < 128)      v = wq[(((size_t)l*4 + (n>>5))*HID + k)*32 + (n&31)];
        else if (n < 256) { int c=n-128; v = wk[(((size_t)l*4 + (c>>5))*HID + k)*32 + (c&31)]; }
        else if (n < 512) { int c=n-256; v = wv[(((size_t)l*4 + (c>>6))*HID + k)*64 + (c&63)]; }
        else              v = wg[((size_t)l*HID + k)*VD + (n-512)];
        g_Wq[(size_t)l*HID*QKN + b16(k, n, 8)] = bf1(v);
    } else {
        int r2 = r - 98304;
        int m = r2 >> 15, e = r2 & 32767;
        if (m == 0){
            int k = e >> 7, n = e & 127;
            g_Wo[(size_t)l*VD*HID + b16(k, n, 16)] =
                bf1(wo[(size_t)l*VD*HID + (size_t)k*HID + n]);
        } else if (m == 1){
            int k = e >> 8, n = e & 255;
            g_W1[(size_t)l*HID*FFND + b16(k, n, 8)] =
                bf1(w1[(size_t)l*HID*FFND + (size_t)k*FFND + n]);
        } else {
            int k = e >> 7, n = e & 127;
            g_W2[(size_t)l*FFND*HID + b16(k, n, 16)] =
                bf1(w2[(size_t)l*FFND*HID + (size_t)k*HID + n]);
        }
    }
}

// ------------------- input MLP -------------------
__global__ __launch_bounds__(256) void rem_kernel(
    const float* __restrict__ x,
    const float* __restrict__ w1, const float* __restrict__ b1,
    const float* __restrict__ w2, const float* __restrict__ b2,
    const float* __restrict__ w3, const float* __restrict__ b3,
    float* __restrict__ X)
{
    __shared__ float sw1[160], sb1[32], sw2[2048], sb2[64], sw3[8192], sb3[128];
    int tid = threadIdx.x;
    for (int i=tid;i<160; i+=256) sw1[i]=w1[i];
    for (int i=tid;i<2048;i+=256) sw2[i]=w2[i];
    for (int i=tid;i<8192;i+=256) sw3[i]=w3[i];
    if (tid<32)  sb1[tid]=b1[tid];
    if (tid<64)  sb2[tid]=b2[tid];
    if (tid<128) sb3[tid]=b3[tid];
    __syncthreads();
    int t = blockIdx.x*256 + tid;
    float xin[5];
#pragma unroll
    for (int k=0;k<5;k++) xin[k] = x[(size_t)t*5+k];
    float h1[32];
#pragma unroll
    for (int o=0;o<32;o++){ float s=sb1[o];
#pragma unroll
        for (int k=0;k<5;k++) s += xin[k]*sw1[k*32+o];
        h1[o]=geluf(s); }
    float h2[64];
#pragma unroll
    for (int o=0;o<64;o++){ float s=sb2[o];
#pragma unroll
        for (int k=0;k<32;k++) s += h1[k]*sw2[k*64+o];
        h2[o]=geluf(s); }
    for (int o=0;o<128;o+=4){
        float v0=sb3[o],v1=sb3[o+1],v2=sb3[o+2],v3=sb3[o+3];
#pragma unroll
        for (int k=0;k<64;k++){ float hk=h2[k];
            v0+=hk*sw3[k*128+o]; v1+=hk*sw3[k*128+o+1];
            v2+=hk*sw3[k*128+o+2]; v3+=hk*sw3[k*128+o+3]; }
        *(float4*)(X+(size_t)t*128+o) = make_float4(geluf(v0),geluf(v1),geluf(v2),geluf(v3));
    }
}

// ------------------- LayerNorm(128) -> bf16 A-fragment layout -------------------
__global__ __launch_bounds__(256) void ln_frag_kernel(
    const float* __restrict__ X, const float* __restrict__ w,
    const float* __restrict__ b, u16* __restrict__ out)
{
    int g = blockIdx.x*256 + threadIdx.x;
    int row = g>>5, lane = g&31;
    float4 v = *(const float4*)(X + (size_t)row*128 + lane*4);
    float s = v.x+v.y+v.z+v.w;
    float s2 = v.x*v.x+v.y*v.y+v.z*v.z+v.w*v.w;
#pragma unroll
    for (int o=16;o;o>>=1){ s += __shfl_xor_sync(~0u,s,o); s2 += __shfl_xor_sync(~0u,s2,o); }
    float mean = s*(1.f/128.f), var = s2*(1.f/128.f)-mean*mean;
    float rstd = rsqrtf(var + 1e-5f);
    float4 wv = *(const float4*)(w+lane*4), bv = *(const float4*)(b+lane*4);
    float rv[4];
    rv[0]=(v.x-mean)*rstd*wv.x+bv.x; rv[1]=(v.y-mean)*rstd*wv.y+bv.y;
    rv[2]=(v.z-mean)*rstd*wv.z+bv.z; rv[3]=(v.w-mean)*rstd*wv.w+bv.w;
    int k0 = lane*4;
    *(unsigned*)(out + a16(row, k0,   8)) = bf2(rv[0], rv[1]);
    *(unsigned*)(out + a16(row, k0+2, 8)) = bf2(rv[2], rv[3]);
}

// ------------------- bf16 frag-fed GEMM (128x64 tile). OP: 1 gelu->Afrag, 3 residual ----
template<int OP>
__global__ __launch_bounds__(256) void gemm_f(
    const u16* __restrict__ Af, const u16* __restrict__ Bf,
    const float* __restrict__ bias, const float* __restrict__ R,
    float* __restrict__ Cf, u16* __restrict__ Ca, int N, int K)
{
    const int tid = threadIdx.x, lane = tid & 31, wid = tid >> 5;
    const int wm = wid & 3, wn = wid >> 2;
    const int m0 = blockIdx.y*128, n0 = blockIdx.x*64;
    const int Kt = K >> 4;

    float acc[2][4][4];
#pragma unroll
    for (int i=0;i<2;i++)
#pragma unroll
        for (int j=0;j<4;j++)
#pragma unroll
            for (int u=0;u<4;u++) acc[i][j][u]=0.f;

    const u16* Ab = Af + ((size_t)((m0>>4) + wm*2))*Kt*256 + lane*8;
    const u16* Bb = Bf + ((size_t)((n0>>3) + wn*4))*Kt*128 + lane*4;

#pragma unroll 2
    for (int kc = 0; kc < Kt; kc++){
        unsigned a[2][4], b[4][2];
#pragma unroll
        for (int mi=0;mi<2;mi++){
            uint4 t = *(const uint4*)(Ab + ((size_t)(mi*Kt + kc))*256);
            a[mi][0]=t.x; a[mi][1]=t.y; a[mi][2]=t.z; a[mi][3]=t.w;
        }
#pragma unroll
        for (int ni=0;ni<4;ni++){
            uint2 t = *(const uint2*)(Bb + ((size_t)(ni*Kt + kc))*128);
            b[ni][0]=t.x; b[ni][1]=t.y;
        }
#pragma unroll
        for (int mi=0;mi<2;mi++)
#pragma unroll
            for (int ni=0;ni<4;ni++)
                mma_bf16(acc[mi][ni], a[mi], b[ni]);
    }

    const int gid = lane>>2, tig = lane&3;
#pragma unroll
    for (int mi=0;mi<2;mi++)
#pragma unroll
        for (int ni=0;ni<4;ni++){
            int col = n0 + wn*32 + ni*8 + tig*2;
            float bb0=0.f, bb1=0.f;
            if (bias){ float2 bv = *(const float2*)(bias+col); bb0=bv.x; bb1=bv.y; }
#pragma unroll
            for (int hh=0; hh<2; hh++){
                int row = m0 + wm*32 + mi*16 + gid + hh*8;
                float v0 = acc[mi][ni][hh*2+0] + bb0;
                float v1 = acc[mi][ni][hh*2+1] + bb1;
                if (OP==1){
                    v0 = geluf(v0); v1 = geluf(v1);
                    *(unsigned*)(Ca + a16(row, col, N>>4)) = bf2(v0, v1);
                } else {
                    float2 rv = *(const float2*)(R + (size_t)row*N + col);
                    v0+=rv.x; v1+=rv.y;
                    *(float2*)(Cf + (size_t)row*N + col) = make_float2(v0,v1);
                }
            }
        }
}

// ------------------- QKVG GEMM: N=768, K=128; epilogue -> per-head bf16 frag buffers ----
__global__ __launch_bounds__(256) void gemm_qkvg(
    const u16* __restrict__ Af, const u16* __restrict__ Bf)
{
    const int tid = threadIdx.x, lane = tid & 31, wid = tid >> 5;
    const int wm = wid & 3, wn = wid >> 2;
    const int m0 = blockIdx.y*128, n0 = blockIdx.x*64;
    const int Kt = 8;

    float acc[2][4][4];
#pragma unroll
    for (int i=0;i<2;i++)
#pragma unroll
        for (int j=0;j<4;j++)
#pragma unroll
            for (int u=0;u<4;u++) acc[i][j][u]=0.f;

    const u16* Ab = Af + ((size_t)((m0>>4) + wm*2))*Kt*256 + lane*8;
    const u16* Bb = Bf + ((size_t)((n0>>3) + wn*4))*Kt*128 + lane*4;

#pragma unroll 2
    for (int kc = 0; kc < Kt; kc++){
        unsigned a[2][4], b[4][2];
#pragma unroll
        for (int mi=0;mi<2;mi++){
            uint4 t = *(const uint4*)(Ab + ((size_t)(mi*Kt + kc))*256);
            a[mi][0]=t.x; a[mi][1]=t.y; a[mi][2]=t.z; a[mi][3]=t.w;
        }
#pragma unroll
        for (int ni=0;ni<4;ni++){
            uint2 t = *(const uint2*)(Bb + ((size_t)(ni*Kt + kc))*128);
            b[ni][0]=t.x; b[ni][1]=t.y;
        }
#pragma unroll
        for (int mi=0;mi<2;mi++)
#pragma unroll
            for (int ni=0;ni<4;ni++)
                mma_bf16(acc[mi][ni], a[mi], b[ni]);
    }

    const int gid = lane>>2, tig = lane&3;
#pragma unroll
    for (int mi=0;mi<2;mi++)
#pragma unroll
        for (int ni=0;ni<4;ni++){
            int col = n0 + wn*32 + ni*8 + tig*2;
#pragma unroll
            for (int hh=0; hh<2; hh++){
                int t = m0 + wm*32 + mi*16 + gid + hh*8;
                int bb = t >> 9, ii = t & 511;
                float v0 = acc[mi][ni][hh*2+0];
                float v1 = acc[mi][ni][hh*2+1];
                if (col < 256){
                    const float* ct = (col<128)? g_qc : g_kc;
                    const float* st = (col<128)? g_qs : g_ks;
                    int j = (col&31)>>1;
                    float c0=ct[ii*16+j], s0=st[ii*16+j];
                    float t0 = v0*c0 - v1*s0, t1 = v1*c0 + v0*s0;
                    if (col < 128){
                        int h = col>>5, d = col&31;
                        float sc = exp2f((float)ii * g_lg2g[h]);
                        u16* dst = g_Qf + ((size_t)(bb*4+h))*16384;
                        *(unsigned*)(dst + a16(ii, d, 2)) = bf2(t0*sc, t1*sc);
                    } else {
                        int h = (col-128)>>5, d = (col-128)&31;
                        float sc = exp2f(-(float)ii * g_lg2g[h]);
                        u16* dst = g_Kf + ((size_t)(bb*4+h))*16384;
                        *(unsigned*)(dst + b16(d, ii, 2)) = bf2(t0*sc, t1*sc);
                    }
                } else if (col < 512){
                    int h = (col-256)>>6, v = (col-256)&63;
                    u16* dst = g_Vf + ((size_t)(bb*4+h))*32768;
                    dst[b16(ii, v,   32)] = bf1(v0);
                    dst[b16(ii, v+1, 32)] = bf1(v1);
                } else {
                    *(float2*)(g_G + (size_t)t*VD + (col-512)) = make_float2(v0, v1);
                }
            }
        }
}

// ------------------- Retention (bf16 mma): Q in regs, coalesced K/V staging -------------------
// dyn smem: Ks u16[2048] @0 (4KB), Vs u16[4096] @4KB (8KB), Sb u16[8192] / Yf f32[8192] @12KB (32KB)
#define RET_SMEM (12288 + 32768)
__global__ __launch_bounds__(256) void retention_kernel(
    const u16* __restrict__ Qf, const u16* __restrict__ Kf,
    const u16* __restrict__ Vf, const float* __restrict__ G,
    const float* __restrict__ gn_w, const float* __restrict__ gn_b,
    u16* __restrict__ P)
{
    extern __shared__ char sm[];
    u16* Ks = (u16*)sm;
    u16* Vs = (u16*)(sm + 4096);
    u16* Sb = (u16*)(sm + 12288);
    float* Yf = (float*)(sm + 12288);

    const int tid = threadIdx.x, lane = tid&31, wm = tid>>5;
    const int gid = lane>>2, tig = lane&3;
    const int qt = blockIdx.x, h = blockIdx.y, b = blockIdx.z;
    const int l0 = qt*128;
    const size_t rb = (size_t)b*512;
    const size_t bh = (size_t)(b*4 + h);
    const u16* Qg = Qf + bh*16384;
    const u16* Kg = Kf + bh*16384;
    const u16* Vg = Vf + bh*32768;

    // Q fragments -> registers (Kt=2)
    unsigned qf[2][4];
#pragma unroll
    for (int kc=0; kc<2; kc++){
        uint4 t = *(const uint4*)(Qg + ((size_t)(((l0>>4)+wm)*2 + kc))*256 + lane*8);
        qf[kc][0]=t.x; qf[kc][1]=t.y; qf[kc][2]=t.z; qf[kc][3]=t.w;
    }

    float yacc[8][4];
#pragma unroll
    for (int j=0;j<8;j++)
#pragma unroll
        for (int u=0;u<4;u++) yacc[j][u]=0.f;

    const int ntile = 2*qt + 2;

    for (int mt=0; mt<ntile; mt++){
        const int doff = mt*64 - l0;
        // stage K (256 uint4, contiguous) + V (512 uint4)
        {
            const uint4* ksrc = (const uint4*)(Kg + (size_t)mt*2048);
            ((uint4*)Ks)[tid] = ksrc[tid];
            uint4* vdst = (uint4*)Vs;
#pragma unroll
            for (int i4 = tid; i4 < 512; i4 += 256){
                int g = i4 >> 6, rem = i4 & 63;
                vdst[g*64 + rem] = ((const uint4*)Vg)[(g*32 + mt*4)*16 + rem];
            }
        }
        __syncthreads();

        // S = Q K^T (decay pre-baked), K=32 -> 2 k16-steps
        float sacc[8][4];
#pragma unroll
        for (int j=0;j<8;j++)
#pragma unroll
            for (int u=0;u<4;u++) sacc[j][u]=0.f;
#pragma unroll
        for (int kc=0; kc<2; kc++){
#pragma unroll
            for (int nj=0;nj<8;nj++){
                uint2 bt = *(const uint2*)(Ks + (size_t)(nj*2+kc)*128 + lane*4);
                unsigned bfr[2] = {bt.x, bt.y};
                mma_bf16(sacc[nj], qf[kc], bfr);
            }
        }
        const bool needmask = (doff >= 0);
#pragma unroll
        for (int nj=0;nj<8;nj++){
            int jb = nj*8 + tig*2;
#pragma unroll
            for (int ih=0; ih<2; ih++){
                int i = wm*16 + gid + ih*8;
                float v0 = sacc[nj][ih*2+0];
                float v1 = sacc[nj][ih*2+1];
                if (needmask){
                    if (i < jb   + doff) v0 = 0.f;
                    if (i < jb+1 + doff) v1 = 0.f;
                }
                *(unsigned*)(Sb + a16(i, jb, 4)) = bf2(v0, v1);
            }
        }
        __syncthreads();

        // Y += S @ V : K=64 -> 4 k16-steps
#pragma unroll
        for (int kc=0; kc<4; kc++){
            unsigned a[4];
            uint4 t = *(const uint4*)(Sb + (size_t)(wm*4+kc)*256 + lane*8);
            a[0]=t.x; a[1]=t.y; a[2]=t.z; a[3]=t.w;
#pragma unroll
            for (int nj=0;nj<8;nj++){
                uint2 bt = *(const uint2*)(Vs + (size_t)(nj*4+kc)*128 + lane*4);
                unsigned bfr[2] = {bt.x, bt.y};
                mma_bf16(yacc[nj], a, bfr);
            }
        }
        __syncthreads();
    }

    // dump Y row-major (fp32) into Yf for group-norm
#pragma unroll
    for (int nj=0;nj<8;nj++){
#pragma unroll
        for (int u=0;u<4;u++){
            int i = wm*16 + gid + (u>>1)*8;
            int j = nj*8 + tig*2 + (u&1);
            Yf[i*64 + j] = yacc[nj][u];
        }
    }
    __syncthreads();

#pragma unroll
    for (int half=0; half<2; half++){
        const int r = (tid>>2) + half*64, q = tid&3;
        float sum=0.f, ssq=0.f;
#pragma unroll
        for (int u=0;u<4;u++){
            float4 v = *(const float4*)&Yf[r*64 + q*16 + u*4];
            sum += v.x+v.y+v.z+v.w;
            ssq += v.x*v.x+v.y*v.y+v.z*v.z+v.w*v.w;
        }
        sum += __shfl_xor_sync(~0u,sum,1); ssq += __shfl_xor_sync(~0u,ssq,1);
        sum += __shfl_xor_sync(~0u,sum,2); ssq += __shfl_xor_sync(~0u,ssq,2);
        float mean = sum*(1.f/64.f), var = ssq*(1.f/64.f)-mean*mean;
        float rstd = rsqrtf(var + 1e-5f);
        const float* gs = G + (rb + l0 + r)*VD + h*64 + q*16;
        const float* gw = gn_w + h*64 + q*16;
        const float* gb = gn_b + h*64 + q*16;
        const int row_t = (int)(rb + l0 + r);
#pragma unroll
        for (int u=0;u<4;u++){
            float4 yv = *(const float4*)&Yf[r*64 + q*16 + u*4];
            float4 gv = *(const float4*)(gs+u*4);
            float4 wv = *(const float4*)(gw+u*4);
            float4 bv = *(const float4*)(gb+u*4);
            float ov[4];
            ov[0] = ((yv.x-mean)*rstd*wv.x+bv.x)*siluf(gv.x);
            ov[1] = ((yv.y-mean)*rstd*wv.y+bv.y)*siluf(gv.y);
            ov[2] = ((yv.z-mean)*rstd*wv.z+bv.z)*siluf(gv.z);
            ov[3] = ((yv.w-mean)*rstd*wv.w+bv.w)*siluf(gv.w);
            int k = h*64 + q*16 + u*4;
            *(unsigned*)(P + a16(row_t, k,   16)) = bf2(ov[0], ov[1]);
            *(unsigned*)(P + a16(row_t, k+2, 16)) = bf2(ov[2], ov[3]);
        }
    }
}

// ------------------- decoder + softmax -------------------
__global__ __launch_bounds__(256) void dec_kernel(
    const float* __restrict__ X, const float* __restrict__ w1, const float* __restrict__ b1,
    const float* __restrict__ w2, const float* __restrict__ b2, float* __restrict__ out)
{
    __shared__ float sw1[8192], sw2[1280], sb1[64], sb2[20];
    int tid = threadIdx.x;
    for (int i=tid;i<8192;i+=256) sw1[i]=w1[i];
    for (int i=tid;i<1280;i+=256) sw2[i]=w2[i];
    if (tid<64) sb1[tid]=b1[tid];
    if (tid<20) sb2[tid]=b2[tid];
    __syncthreads();
    int t = blockIdx.x*256 + tid;
    float h[64];
#pragma unroll
    for (int o=0;o<64;o++) h[o]=sb1[o];
    for (int k=0;k<128;k+=4){
        float4 xv = *(const float4*)(X + (size_t)t*128 + k);
#pragma unroll
        for (int o=0;o<64;o++){
            h[o] += xv.x*sw1[(k+0)*64+o] + xv.y*sw1[(k+1)*64+o]
                  + xv.z*sw1[(k+2)*64+o] + xv.w*sw1[(k+3)*64+o];
        }
    }
#pragma unroll
    for (int o=0;o<64;o++) h[o]=geluf(h[o]);
    float lg[20];
#pragma unroll
    for (int o=0;o<20;o++){ float s=sb2[o];
#pragma unroll
        for (int k=0;k<64;k++) s += h[k]*sw2[k*20+o];
        lg[o]=s; }
    float mx = lg[0];
#pragma unroll
    for (int o=1;o<20;o++) mx = fmaxf(mx, lg[o]);
    float sum = 0.f;
#pragma unroll
    for (int o=0;o<20;o++){ lg[o] = expf(lg[o]-mx); sum += lg[o]; }
    float inv = 1.0f/sum;
#pragma unroll
    for (int o=0;o<20;o++) out[(size_t)t*20+o] = lg[o]*inv;
}

// ------------------- launch -------------------
extern "C" void kernel_launch(void* const* d_in, const int* in_sizes, int n_in,
                              void* d_out, int out_size)
{
    const float* x      = (const float*)d_in[0];
    const float* rem_w1 = (const float*)d_in[1];
    const float* rem_b1 = (const float*)d_in[2];
    const float* rem_w2 = (const float*)d_in[3];
    const float* rem_b2 = (const float*)d_in[4];
    const float* rem_w3 = (const float*)d_in[5];
    const float* rem_b3 = (const float*)d_in[6];
    const float* wq     = (const float*)d_in[7];
    const float* wk     = (const float*)d_in[8];
    const float* wv     = (const float*)d_in[9];
    const float* wg     = (const float*)d_in[10];
    const float* wo     = (const float*)d_in[11];
    const float* gn_w   = (const float*)d_in[12];
    const float* gn_b   = (const float*)d_in[13];
    const float* ln1_w  = (const float*)d_in[14];
    const float* ln1_b  = (const float*)d_in[15];
    const float* ln2_w  = (const float*)d_in[16];
    const float* ln2_b  = (const float*)d_in[17];
    const float* ffn_w1 = (const float*)d_in[18];
    const float* ffn_b1 = (const float*)d_in[19];
    const float* ffn_w2 = (const float*)d_in[20];
    const float* ffn_b2 = (const float*)d_in[21];
    const float* dec_w1 = (const float*)d_in[22];
    const float* dec_b1 = (const float*)d_in[23];
    const float* dec_w2 = (const float*)d_in[24];
    const float* dec_b2 = (const float*)d_in[25];
    float* out = (float*)d_out;

    float *pX,*pY1,*pG;
    u16 *pXn,*pP,*pHf,*pWq,*pWo,*pW1,*pW2,*pQf,*pKf,*pVf;
    cudaGetSymbolAddress((void**)&pX,  g_X);
    cudaGetSymbolAddress((void**)&pY1, g_Y1);
    cudaGetSymbolAddress((void**)&pG,  g_G);
    cudaGetSymbolAddress((void**)&pXn, g_Xn);
    cudaGetSymbolAddress((void**)&pP,  g_P);
    cudaGetSymbolAddress((void**)&pHf, g_Hf);
    cudaGetSymbolAddress((void**)&pWq, g_Wq);
    cudaGetSymbolAddress((void**)&pWo, g_Wo);
    cudaGetSymbolAddress((void**)&pW1, g_W1);
    cudaGetSymbolAddress((void**)&pW2, g_W2);
    cudaGetSymbolAddress((void**)&pQf, g_Qf);
    cudaGetSymbolAddress((void**)&pKf, g_Kf);
    cudaGetSymbolAddress((void**)&pVf, g_Vf);

    cudaFuncSetAttribute(retention_kernel,
        cudaFuncAttributeMaxDynamicSharedMemorySize, RET_SMEM);

    xpos_table_kernel<<<32, 256>>>();
    wfrag_all_kernel<<<(4*196608)/256, 256>>>(wq, wk, wv, wg, wo, ffn_w1, ffn_w2);
    rem_kernel<<<TOKENS/256, 256>>>(x, rem_w1, rem_b1, rem_w2, rem_b2, rem_w3, rem_b3, pX);

    for (int l = 0; l < 4; l++){
        ln_frag_kernel<<<TOKENS/8, 256>>>(pX, ln1_w + l*128, ln1_b + l*128, pXn);
        gemm_qkvg<<<dim3(QKN/64, TOKENS/128), 256>>>(pXn, pWq + (size_t)l*HID*QKN);
        retention_kernel<<<dim3(4, 4, 64), 256, RET_SMEM>>>(
            pQf, pKf, pVf, pG, gn_w + l*VD, gn_b + l*VD, pP);
        gemm_f<3><<<dim3(HID/64, TOKENS/128), 256>>>(
            pP, pWo + (size_t)l*VD*HID, nullptr, pX, pY1, nullptr, HID, VD);
        ln_frag_kernel<<<TOKENS/8, 256>>>(pY1, ln2_w + l*128, ln2_b + l*128, pXn);
        gemm_f<1><<<dim3(FFND/64, TOKENS/128), 256>>>(
            pXn, pW1 + (size_t)l*HID*FFND, ffn_b1 + l*FFND, nullptr, nullptr, pHf, FFND, HID);
        gemm_f<3><<<dim3(HID/64, TOKENS/128), 256>>>(
            pHf, pW2 + (size_t)l*FFND*HID, ffn_b2 + l*HID, pY1, pX, nullptr, HID, FFND);
    }
    dec_kernel<<<TOKENS/256, 256>>>(pX, dec_w1, dec_b1, dec_w2, dec_b2, out);
}

// round 12
// speedup vs baseline: 2.1696x; 1.1409x over previous
#include <cuda_runtime.h>
#include <cuda_bf16.h>
#include <math.h>
#include <stdint.h>

#define TOKENS 32768
#define LSEQ   512
#define HID    128
#define VD     256
#define FFND   256
#define QKN    768   // 128 Q | 128 K | 256 V | 256 G

typedef unsigned short u16;

// fp32 row-major buffers
__device__ float g_X [TOKENS * HID];
__device__ float g_Y1[TOKENS * HID];
// bf16 buffers
__device__ u16 g_G [TOKENS * VD];
__device__ u16 g_Xn[TOKENS * HID];
__device__ u16 g_P [TOKENS * VD];
__device__ u16 g_Hf[TOKENS * FFND];
__device__ u16 g_Qf[64*4*16384];
__device__ u16 g_Kf[64*4*16384];
__device__ u16 g_Vf[(size_t)64*4*32768];
__device__ u16 g_Wq[4 * HID * QKN];
__device__ u16 g_Wo[4 * VD * HID];
__device__ u16 g_W1[4 * HID * FFND];
__device__ u16 g_W2[4 * FFND * HID];
__device__ float g_qc[LSEQ*16], g_qs[LSEQ*16], g_kc[LSEQ*16], g_ks[LSEQ*16];
__device__ float g_lg2g[4];

__device__ __forceinline__ float geluf(float v){ return 0.5f*v*(1.0f+erff(v*0.70710678f)); }
__device__ __forceinline__ float siluf(float v){ return v/(1.0f+expf(-v)); }
__device__ __forceinline__ unsigned bf2(float a, float b){
    __nv_bfloat162 t = __floats2bfloat162_rn(a, b);
    return *(unsigned*)&t;
}
__device__ __forceinline__ u16 bf1(float a){
    __nv_bfloat16 t = __float2bfloat16_rn(a);
    return *(u16*)&t;
}
__device__ __forceinline__ float2 unbf2(unsigned u){
    __nv_bfloat162 t = *(__nv_bfloat162*)&u;
    return __bfloat1622float2(t);
}
__device__ __forceinline__ void mma_bf16(float* d, const unsigned* a, const unsigned* b){
    asm volatile("mma.sync.aligned.m16n8k16.row.col.f32.bf16.bf16.f32 "
        "{%0,%1,%2,%3},{%4,%5,%6,%7},{%8,%9},{%0,%1,%2,%3};"
        : "+f"(d[0]),"+f"(d[1]),"+f"(d[2]),"+f"(d[3])
        : "r"(a[0]),"r"(a[1]),"r"(a[2]),"r"(a[3]), "r"(b[0]),"r"(b[1]));
}

// A-fragment ushort index, m16n8k16 bf16. Kt = K/16.
__device__ __forceinline__ size_t a16(int row, int k, int Kt){
    return ((size_t)((row>>4)*Kt + (k>>4)))*256 +
           (size_t)(((row&7)*4 + ((k&7)>>1))*8 + (((row>>3)&1) + (((k>>3)&1)<<1))*2 + (k&1));
}
// B-fragment ushort index
__device__ __forceinline__ size_t b16(int k, int n, int Kt){
    return ((size_t)((n>>3)*Kt + (k>>4)))*128 +
           (size_t)(((n&7)*4 + ((k&7)>>1))*4 + (((k>>3)&1)<<1) + (k&1));
}

// ------------------- xpos tables + per-head log2(gamma) -------------------
__global__ void xpos_table_kernel(){
    int idx = blockIdx.x*256 + threadIdx.x;
    if (idx < 4){
        double lgA=-3.4657359027997265, lgB=-6.2383246250395075;
        g_lg2g[idx] = (float)(log(1.0 - exp(lgA + (lgB-lgA)*(double)idx/3.0)) * 1.4426950408889634);
    }
    if (idx >= LSEQ*16) return;
    int l = idx >> 4, j = idx & 15;
    float base = ((float)j + 12.8f) / 44.8f;
    float sc   = powf(base, (float)l / 512.0f);
    float ang  = (float)l * powf(10000.0f, -(float)j/16.0f);
    float s, c; sincosf(ang, &s, &c);
    g_qc[idx]=c*sc; g_qs[idx]=s*sc; g_kc[idx]=c/sc; g_ks[idx]=s/sc;
}

// ------------------- ALL weights -> bf16 B-fragment layout -------------------
__global__ void wfrag_all_kernel(
    const float* __restrict__ wq, const float* __restrict__ wk,
    const float* __restrict__ wv, const float* __restrict__ wg,
    const float* __restrict__ wo, const float* __restrict__ w1,
    const float* __restrict__ w2)
{
    int idx = blockIdx.x*256 + threadIdx.x;
    int l = idx / 196608, r = idx % 196608;
    if (r < 98304){
        int k = r / QKN, n = r % QKN;
        float v;
        if (n < 128)      v = wq[(((size_t)l*4 + (n>>5))*HID + k)*32 + (n&31)];
        else if (n < 256) { int c=n-128; v = wk[(((size_t)l*4 + (c>>5))*HID + k)*32 + (c&31)]; }
        else if (n < 512) { int c=n-256; v = wv[(((size_t)l*4 + (c>>6))*HID + k)*64 + (c&63)]; }
        else              v = wg[((size_t)l*HID + k)*VD + (n-512)];
        g_Wq[(size_t)l*HID*QKN + b16(k, n, 8)] = bf1(v);
    } else {
        int r2 = r - 98304;
        int m = r2 >> 15, e = r2 & 32767;
        if (m == 0){
            int k = e >> 7, n = e & 127;
            g_Wo[(size_t)l*VD*HID + b16(k, n, 16)] =
                bf1(wo[(size_t)l*VD*HID + (size_t)k*HID + n]);
        } else if (m == 1){
            int k = e >> 8, n = e & 255;
            g_W1[(size_t)l*HID*FFND + b16(k, n, 8)] =
                bf1(w1[(size_t)l*HID*FFND + (size_t)k*FFND + n]);
        } else {
            int k = e >> 7, n = e & 127;
            g_W2[(size_t)l*FFND*HID + b16(k, n, 16)] =
                bf1(w2[(size_t)l*FFND*HID + (size_t)k*HID + n]);
        }
    }
}

// ------------------- input MLP -------------------
__global__ __launch_bounds__(256) void rem_kernel(
    const float* __restrict__ x,
    const float* __restrict__ w1, const float* __restrict__ b1,
    const float* __restrict__ w2, const float* __restrict__ b2,
    const float* __restrict__ w3, const float* __restrict__ b3,
    float* __restrict__ X)
{
    __shared__ float sw1[160], sb1[32], sw2[2048], sb2[64], sw3[8192], sb3[128];
    int tid = threadIdx.x;
    for (int i=tid;i<160; i+=256) sw1[i]=w1[i];
    for (int i=tid;i<2048;i+=256) sw2[i]=w2[i];
    for (int i=tid;i<8192;i+=256) sw3[i]=w3[i];
    if (tid<32)  sb1[tid]=b1[tid];
    if (tid<64)  sb2[tid]=b2[tid];
    if (tid<128) sb3[tid]=b3[tid];
    __syncthreads();
    int t = blockIdx.x*256 + tid;
    float xin[5];
#pragma unroll
    for (int k=0;k<5;k++) xin[k] = x[(size_t)t*5+k];
    float h1[32];
#pragma unroll
    for (int o=0;o<32;o++){ float s=sb1[o];
#pragma unroll
        for (int k=0;k<5;k++) s += xin[k]*sw1[k*32+o];
        h1[o]=geluf(s); }
    float h2[64];
#pragma unroll
    for (int o=0;o<64;o++){ float s=sb2[o];
#pragma unroll
        for (int k=0;k<32;k++) s += h1[k]*sw2[k*64+o];
        h2[o]=geluf(s); }
    for (int o=0;o<128;o+=4){
        float v0=sb3[o],v1=sb3[o+1],v2=sb3[o+2],v3=sb3[o+3];
#pragma unroll
        for (int k=0;k<64;k++){ float hk=h2[k];
            v0+=hk*sw3[k*128+o]; v1+=hk*sw3[k*128+o+1];
            v2+=hk*sw3[k*128+o+2]; v3+=hk*sw3[k*128+o+3]; }
        *(float4*)(X+(size_t)t*128+o) = make_float4(geluf(v0),geluf(v1),geluf(v2),geluf(v3));
    }
}

// ------------------- LayerNorm(128) -> bf16 A-fragment layout -------------------
__global__ __launch_bounds__(256) void ln_frag_kernel(
    const float* __restrict__ X, const float* __restrict__ w,
    const float* __restrict__ b, u16* __restrict__ out)
{
    int g = blockIdx.x*256 + threadIdx.x;
    int row = g>>5, lane = g&31;
    float4 v = *(const float4*)(X + (size_t)row*128 + lane*4);
    float s = v.x+v.y+v.z+v.w;
    float s2 = v.x*v.x+v.y*v.y+v.z*v.z+v.w*v.w;
#pragma unroll
    for (int o=16;o;o>>=1){ s += __shfl_xor_sync(~0u,s,o); s2 += __shfl_xor_sync(~0u,s2,o); }
    float mean = s*(1.f/128.f), var = s2*(1.f/128.f)-mean*mean;
    float rstd = rsqrtf(var + 1e-5f);
    float4 wv = *(const float4*)(w+lane*4), bv = *(const float4*)(b+lane*4);
    float rv[4];
    rv[0]=(v.x-mean)*rstd*wv.x+bv.x; rv[1]=(v.y-mean)*rstd*wv.y+bv.y;
    rv[2]=(v.z-mean)*rstd*wv.z+bv.z; rv[3]=(v.w-mean)*rstd*wv.w+bv.w;
    int k0 = lane*4;
    *(unsigned*)(out + a16(row, k0,   8)) = bf2(rv[0], rv[1]);
    *(unsigned*)(out + a16(row, k0+2, 8)) = bf2(rv[2], rv[3]);
}

// ------------------- bf16 frag-fed GEMM, 256x64 block, warp 64x32. OP: 1 gelu->Afrag, 3 residual ----
template<int OP>
__global__ __launch_bounds__(256) void gemm_f(
    const u16* __restrict__ Af, const u16* __restrict__ Bf,
    const float* __restrict__ bias, const float* __restrict__ R,
    float* __restrict__ Cf, u16* __restrict__ Ca, int N, int K)
{
    const int tid = threadIdx.x, lane = tid & 31, wid = tid >> 5;
    const int wm = wid & 3, wn = wid >> 2;
    const int m0 = blockIdx.y*256, n0 = blockIdx.x*64;
    const int Kt = K >> 4;

    float acc[4][4][4];
#pragma unroll
    for (int i=0;i<4;i++)
#pragma unroll
        for (int j=0;j<4;j++)
#pragma unroll
            for (int u=0;u<4;u++) acc[i][j][u]=0.f;

    const u16* Ab = Af + ((size_t)((m0>>4) + wm*4))*Kt*256 + lane*8;
    const u16* Bb = Bf + ((size_t)((n0>>3) + wn*4))*Kt*128 + lane*4;

#pragma unroll 2
    for (int kc = 0; kc < Kt; kc++){
        unsigned a[4][4], b[4][2];
#pragma unroll
        for (int mi=0;mi<4;mi++){
            uint4 t = *(const uint4*)(Ab + ((size_t)(mi*Kt + kc))*256);
            a[mi][0]=t.x; a[mi][1]=t.y; a[mi][2]=t.z; a[mi][3]=t.w;
        }
#pragma unroll
        for (int ni=0;ni<4;ni++){
            uint2 t = *(const uint2*)(Bb + ((size_t)(ni*Kt + kc))*128);
            b[ni][0]=t.x; b[ni][1]=t.y;
        }
#pragma unroll
        for (int mi=0;mi<4;mi++)
#pragma unroll
            for (int ni=0;ni<4;ni++)
                mma_bf16(acc[mi][ni], a[mi], b[ni]);
    }

    const int gid = lane>>2, tig = lane&3;
#pragma unroll
    for (int mi=0;mi<4;mi++)
#pragma unroll
        for (int ni=0;ni<4;ni++){
            int col = n0 + wn*32 + ni*8 + tig*2;
            float bb0=0.f, bb1=0.f;
            if (bias){ float2 bv = *(const float2*)(bias+col); bb0=bv.x; bb1=bv.y; }
#pragma unroll
            for (int hh=0; hh<2; hh++){
                int row = m0 + wm*64 + mi*16 + gid + hh*8;
                float v0 = acc[mi][ni][hh*2+0] + bb0;
                float v1 = acc[mi][ni][hh*2+1] + bb1;
                if (OP==1){
                    v0 = geluf(v0); v1 = geluf(v1);
                    *(unsigned*)(Ca + a16(row, col, N>>4)) = bf2(v0, v1);
                } else {
                    float2 rv = *(const float2*)(R + (size_t)row*N + col);
                    v0+=rv.x; v1+=rv.y;
                    *(float2*)(Cf + (size_t)row*N + col) = make_float2(v0,v1);
                }
            }
        }
}

// ------------------- QKVG GEMM: 256x64 block, epilogue -> per-head bf16 frag buffers ----
__global__ __launch_bounds__(256) void gemm_qkvg(
    const u16* __restrict__ Af, const u16* __restrict__ Bf)
{
    const int tid = threadIdx.x, lane = tid & 31, wid = tid >> 5;
    const int wm = wid & 3, wn = wid >> 2;
    const int m0 = blockIdx.y*256, n0 = blockIdx.x*64;
    const int Kt = 8;

    float acc[4][4][4];
#pragma unroll
    for (int i=0;i<4;i++)
#pragma unroll
        for (int j=0;j<4;j++)
#pragma unroll
            for (int u=0;u<4;u++) acc[i][j][u]=0.f;

    const u16* Ab = Af + ((size_t)((m0>>4) + wm*4))*Kt*256 + lane*8;
    const u16* Bb = Bf + ((size_t)((n0>>3) + wn*4))*Kt*128 + lane*4;

#pragma unroll 2
    for (int kc = 0; kc < Kt; kc++){
        unsigned a[4][4], b[4][2];
#pragma unroll
        for (int mi=0;mi<4;mi++){
            uint4 t = *(const uint4*)(Ab + ((size_t)(mi*Kt + kc))*256);
            a[mi][0]=t.x; a[mi][1]=t.y; a[mi][2]=t.z; a[mi][3]=t.w;
        }
#pragma unroll
        for (int ni=0;ni<4;ni++){
            uint2 t = *(const uint2*)(Bb + ((size_t)(ni*Kt + kc))*128);
            b[ni][0]=t.x; b[ni][1]=t.y;
        }
#pragma unroll
        for (int mi=0;mi<4;mi++)
#pragma unroll
            for (int ni=0;ni<4;ni++)
                mma_bf16(acc[mi][ni], a[mi], b[ni]);
    }

    const int gid = lane>>2, tig = lane&3;
#pragma unroll
    for (int mi=0;mi<4;mi++)
#pragma unroll
        for (int ni=0;ni<4;ni++){
            int col = n0 + wn*32 + ni*8 + tig*2;
#pragma unroll
            for (int hh=0; hh<2; hh++){
                int t = m0 + wm*64 + mi*16 + gid + hh*8;
                int bb = t >> 9, ii = t & 511;
                float v0 = acc[mi][ni][hh*2+0];
                float v1 = acc[mi][ni][hh*2+1];
                if (col < 256){
                    const float* ct = (col<128)? g_qc : g_kc;
                    const float* st = (col<128)? g_qs : g_ks;
                    int j = (col&31)>>1;
                    float c0=ct[ii*16+j], s0=st[ii*16+j];
                    float t0 = v0*c0 - v1*s0, t1 = v1*c0 + v0*s0;
                    if (col < 128){
                        int h = col>>5, d = col&31;
                        float sc = exp2f((float)ii * g_lg2g[h]);
                        u16* dst = g_Qf + ((size_t)(bb*4+h))*16384;
                        *(unsigned*)(dst + a16(ii, d, 2)) = bf2(t0*sc, t1*sc);
                    } else {
                        int h = (col-128)>>5, d = (col-128)&31;
                        float sc = exp2f(-(float)ii * g_lg2g[h]);
                        u16* dst = g_Kf + ((size_t)(bb*4+h))*16384;
                        *(unsigned*)(dst + b16(d, ii, 2)) = bf2(t0*sc, t1*sc);
                    }
                } else if (col < 512){
                    int h = (col-256)>>6, v = (col-256)&63;
                    u16* dst = g_Vf + ((size_t)(bb*4+h))*32768;
                    dst[b16(ii, v,   32)] = bf1(v0);
                    dst[b16(ii, v+1, 32)] = bf1(v1);
                } else {
                    *(unsigned*)(g_G + (size_t)t*VD + (col-512)) = bf2(v0, v1);
                }
            }
        }
}

// ------------------- Retention (bf16 mma): Q in regs, coalesced K/V staging -------------------
#define RET_SMEM (12288 + 32768)
__global__ __launch_bounds__(256) void retention_kernel(
    const u16* __restrict__ Qf, const u16* __restrict__ Kf,
    const u16* __restrict__ Vf, const u16* __restrict__ G,
    const float* __restrict__ gn_w, const float* __restrict__ gn_b,
    u16* __restrict__ P)
{
    extern __shared__ char sm[];
    u16* Ks = (u16*)sm;
    u16* Vs = (u16*)(sm + 4096);
    u16* Sb = (u16*)(sm + 12288);
    float* Yf = (float*)(sm + 12288);

    const int tid = threadIdx.x, lane = tid&31, wm = tid>>5;
    const int gid = lane>>2, tig = lane&3;
    const int qt = blockIdx.x, h = blockIdx.y, b = blockIdx.z;
    const int l0 = qt*128;
    const size_t rb = (size_t)b*512;
    const size_t bh = (size_t)(b*4 + h);
    const u16* Qg = Qf + bh*16384;
    const u16* Kg = Kf + bh*16384;
    const u16* Vg = Vf + bh*32768;

    unsigned qf[2][4];
#pragma unroll
    for (int kc=0; kc<2; kc++){
        uint4 t = *(const uint4*)(Qg + ((size_t)(((l0>>4)+wm)*2 + kc))*256 + lane*8);
        qf[kc][0]=t.x; qf[kc][1]=t.y; qf[kc][2]=t.z; qf[kc][3]=t.w;
    }

    float yacc[8][4];
#pragma unroll
    for (int j=0;j<8;j++)
#pragma unroll
        for (int u=0;u<4;u++) yacc[j][u]=0.f;

    const int ntile = 2*qt + 2;

    for (int mt=0; mt<ntile; mt++){
        const int doff = mt*64 - l0;
        {
            const uint4* ksrc = (const uint4*)(Kg + (size_t)mt*2048);
            ((uint4*)Ks)[tid] = ksrc[tid];
            uint4* vdst = (uint4*)Vs;
#pragma unroll
            for (int i4 = tid; i4 < 512; i4 += 256){
                int g = i4 >> 6, rem = i4 & 63;
                vdst[g*64 + rem] = ((const uint4*)Vg)[(g*32 + mt*4)*16 + rem];
            }
        }
        __syncthreads();

        float sacc[8][4];
#pragma unroll
        for (int j=0;j<8;j++)
#pragma unroll
            for (int u=0;u<4;u++) sacc[j][u]=0.f;
#pragma unroll
        for (int kc=0; kc<2; kc++){
#pragma unroll
            for (int nj=0;nj<8;nj++){
                uint2 bt = *(const uint2*)(Ks + (size_t)(nj*2+kc)*128 + lane*4);
                unsigned bfr[2] = {bt.x, bt.y};
                mma_bf16(sacc[nj], qf[kc], bfr);
            }
        }
        const bool needmask = (doff >= 0);
#pragma unroll
        for (int nj=0;nj<8;nj++){
            int jb = nj*8 + tig*2;
#pragma unroll
            for (int ih=0; ih<2; ih++){
                int i = wm*16 + gid + ih*8;
                float v0 = sacc[nj][ih*2+0];
                float v1 = sacc[nj][ih*2+1];
                if (needmask){
                    if (i < jb   + doff) v0 = 0.f;
                    if (i < jb+1 + doff) v1 = 0.f;
                }
                *(unsigned*)(Sb + a16(i, jb, 4)) = bf2(v0, v1);
            }
        }
        __syncthreads();

#pragma unroll
        for (int kc=0; kc<4; kc++){
            unsigned a[4];
            uint4 t = *(const uint4*)(Sb + (size_t)(wm*4+kc)*256 + lane*8);
            a[0]=t.x; a[1]=t.y; a[2]=t.z; a[3]=t.w;
#pragma unroll
            for (int nj=0;nj<8;nj++){
                uint2 bt = *(const uint2*)(Vs + (size_t)(nj*4+kc)*128 + lane*4);
                unsigned bfr[2] = {bt.x, bt.y};
                mma_bf16(yacc[nj], a, bfr);
            }
        }
        __syncthreads();
    }

#pragma unroll
    for (int nj=0;nj<8;nj++){
#pragma unroll
        for (int u=0;u<4;u++){
            int i = wm*16 + gid + (u>>1)*8;
            int j = nj*8 + tig*2 + (u&1);
            Yf[i*64 + j] = yacc[nj][u];
        }
    }
    __syncthreads();

#pragma unroll
    for (int half=0; half<2; half++){
        const int r = (tid>>2) + half*64, q = tid&3;
        float sum=0.f, ssq=0.f;
#pragma unroll
        for (int u=0;u<4;u++){
            float4 v = *(const float4*)&Yf[r*64 + q*16 + u*4];
            sum += v.x+v.y+v.z+v.w;
            ssq += v.x*v.x+v.y*v.y+v.z*v.z+v.w*v.w;
        }
        sum += __shfl_xor_sync(~0u,sum,1); ssq += __shfl_xor_sync(~0u,ssq,1);
        sum += __shfl_xor_sync(~0u,sum,2); ssq += __shfl_xor_sync(~0u,ssq,2);
        float mean = sum*(1.f/64.f), var = ssq*(1.f/64.f)-mean*mean;
        float rstd = rsqrtf(var + 1e-5f);
        const u16* gs = G + (rb + l0 + r)*VD + h*64 + q*16;
        const float* gw = gn_w + h*64 + q*16;
        const float* gb = gn_b + h*64 + q*16;
        const int row_t = (int)(rb + l0 + r);
#pragma unroll
        for (int u=0;u<4;u++){
            float4 yv = *(const float4*)&Yf[r*64 + q*16 + u*4];
            uint2 gp = *(const uint2*)(gs + u*4);
            float2 g01 = unbf2(gp.x), g23 = unbf2(gp.y);
            float4 wv = *(const float4*)(gw+u*4);
            float4 bv = *(const float4*)(gb+u*4);
            float ov[4];
            ov[0] = ((yv.x-mean)*rstd*wv.x+bv.x)*siluf(g01.x);
            ov[1] = ((yv.y-mean)*rstd*wv.y+bv.y)*siluf(g01.y);
            ov[2] = ((yv.z-mean)*rstd*wv.z+bv.z)*siluf(g23.x);
            ov[3] = ((yv.w-mean)*rstd*wv.w+bv.w)*siluf(g23.y);
            int k = h*64 + q*16 + u*4;
            *(unsigned*)(P + a16(row_t, k,   16)) = bf2(ov[0], ov[1]);
            *(unsigned*)(P + a16(row_t, k+2, 16)) = bf2(ov[2], ov[3]);
        }
    }
}

// ------------------- decoder + softmax -------------------
__global__ __launch_bounds__(256) void dec_kernel(
    const float* __restrict__ X, const float* __restrict__ w1, const float* __restrict__ b1,
    const float* __restrict__ w2, const float* __restrict__ b2, float* __restrict__ out)
{
    __shared__ float sw1[8192], sw2[1280], sb1[64], sb2[20];
    int tid = threadIdx.x;
    for (int i=tid;i<8192;i+=256) sw1[i]=w1[i];
    for (int i=tid;i<1280;i+=256) sw2[i]=w2[i];
    if (tid<64) sb1[tid]=b1[tid];
    if (tid<20) sb2[tid]=b2[tid];
    __syncthreads();
    int t = blockIdx.x*256 + tid;
    float h[64];
#pragma unroll
    for (int o=0;o<64;o++) h[o]=sb1[o];
    for (int k=0;k<128;k+=4){
        float4 xv = *(const float4*)(X + (size_t)t*128 + k);
#pragma unroll
        for (int o=0;o<64;o++){
            h[o] += xv.x*sw1[(k+0)*64+o] + xv.y*sw1[(k+1)*64+o]
                  + xv.z*sw1[(k+2)*64+o] + xv.w*sw1[(k+3)*64+o];
        }
    }
#pragma unroll
    for (int o=0;o<64;o++) h[o]=geluf(h[o]);
    float lg[20];
#pragma unroll
    for (int o=0;o<20;o++){ float s=sb2[o];
#pragma unroll
        for (int k=0;k<64;k++) s += h[k]*sw2[k*20+o];
        lg[o]=s; }
    float mx = lg[0];
#pragma unroll
    for (int o=1;o<20;o++) mx = fmaxf(mx, lg[o]);
    float sum = 0.f;
#pragma unroll
    for (int o=0;o<20;o++){ lg[o] = expf(lg[o]-mx); sum += lg[o]; }
    float inv = 1.0f/sum;
#pragma unroll
    for (int o=0;o<20;o++) out[(size_t)t*20+o] = lg[o]*inv;
}

// ------------------- launch -------------------
extern "C" void kernel_launch(void* const* d_in, const int* in_sizes, int n_in,
                              void* d_out, int out_size)
{
    const float* x      = (const float*)d_in[0];
    const float* rem_w1 = (const float*)d_in[1];
    const float* rem_b1 = (const float*)d_in[2];
    const float* rem_w2 = (const float*)d_in[3];
    const float* rem_b2 = (const float*)d_in[4];
    const float* rem_w3 = (const float*)d_in[5];
    const float* rem_b3 = (const float*)d_in[6];
    const float* wq     = (const float*)d_in[7];
    const float* wk     = (const float*)d_in[8];
    const float* wv     = (const float*)d_in[9];
    const float* wg     = (const float*)d_in[10];
    const float* wo     = (const float*)d_in[11];
    const float* gn_w   = (const float*)d_in[12];
    const float* gn_b   = (const float*)d_in[13];
    const float* ln1_w  = (const float*)d_in[14];
    const float* ln1_b  = (const float*)d_in[15];
    const float* ln2_w  = (const float*)d_in[16];
    const float* ln2_b  = (const float*)d_in[17];
    const float* ffn_w1 = (const float*)d_in[18];
    const float* ffn_b1 = (const float*)d_in[19];
    const float* ffn_w2 = (const float*)d_in[20];
    const float* ffn_b2 = (const float*)d_in[21];
    const float* dec_w1 = (const float*)d_in[22];
    const float* dec_b1 = (const float*)d_in[23];
    const float* dec_w2 = (const float*)d_in[24];
    const float* dec_b2 = (const float*)d_in[25];
    float* out = (float*)d_out;

    float *pX,*pY1;
    u16 *pG,*pXn,*pP,*pHf,*pWq,*pWo,*pW1,*pW2,*pQf,*pKf,*pVf;
    cudaGetSymbolAddress((void**)&pX,  g_X);
    cudaGetSymbolAddress((void**)&pY1, g_Y1);
    cudaGetSymbolAddress((void**)&pG,  g_G);
    cudaGetSymbolAddress((void**)&pXn, g_Xn);
    cudaGetSymbolAddress((void**)&pP,  g_P);
    cudaGetSymbolAddress((void**)&pHf, g_Hf);
    cudaGetSymbolAddress((void**)&pWq, g_Wq);
    cudaGetSymbolAddress((void**)&pWo, g_Wo);
    cudaGetSymbolAddress((void**)&pW1, g_W1);
    cudaGetSymbolAddress((void**)&pW2, g_W2);
    cudaGetSymbolAddress((void**)&pQf, g_Qf);
    cudaGetSymbolAddress((void**)&pKf, g_Kf);
    cudaGetSymbolAddress((void**)&pVf, g_Vf);

    cudaFuncSetAttribute(retention_kernel,
        cudaFuncAttributeMaxDynamicSharedMemorySize, RET_SMEM);

    xpos_table_kernel<<<32, 256>>>();
    wfrag_all_kernel<<<(4*196608)/256, 256>>>(wq, wk, wv, wg, wo, ffn_w1, ffn_w2);
    rem_kernel<<<TOKENS/256, 256>>>(x, rem_w1, rem_b1, rem_w2, rem_b2, rem_w3, rem_b3, pX);

    for (int l = 0; l < 4; l++){
        ln_frag_kernel<<<TOKENS/8, 256>>>(pX, ln1_w + l*128, ln1_b + l*128, pXn);
        gemm_qkvg<<<dim3(QKN/64, TOKENS/256), 256>>>(pXn, pWq + (size_t)l*HID*QKN);
        retention_kernel<<<dim3(4, 4, 64), 256, RET_SMEM>>>(
            pQf, pKf, pVf, pG, gn_w + l*VD, gn_b + l*VD, pP);
        gemm_f<3><<<dim3(HID/64, TOKENS/256), 256>>>(
            pP, pWo + (size_t)l*VD*HID, nullptr, pX, pY1, nullptr, HID, VD);
        ln_frag_kernel<<<TOKENS/8, 256>>>(pY1, ln2_w + l*128, ln2_b + l*128, pXn);
        gemm_f<1><<<dim3(FFND/64, TOKENS/256), 256>>>(
            pXn, pW1 + (size_t)l*HID*FFND, ffn_b1 + l*FFND, nullptr, nullptr, pHf, FFND, HID);
        gemm_f<3><<<dim3(HID/64, TOKENS/256), 256>>>(
            pHf, pW2 + (size_t)l*FFND*HID, ffn_b2 + l*HID, pY1, pX, nullptr, HID, FFND);
    }
    dec_kernel<<<TOKENS/256, 256>>>(pX, dec_w1, dec_b1, dec_w2, dec_b2, out);
}

// round 13
// speedup vs baseline: 2.4767x; 1.1415x over previous
#include <cuda_runtime.h>
#include <cuda_bf16.h>
#include <math.h>
#include <stdint.h>

#define TOKENS 32768
#define LSEQ   512
#define HID    128
#define VD     256
#define FFND   256
#define QKN    768   // 128 Q | 128 K | 256 V | 256 G

typedef unsigned short u16;

// fp32 row-major buffers
__device__ float g_X [TOKENS * HID];
__device__ float g_Y1[TOKENS * HID];
// bf16 buffers
__device__ u16 g_G [TOKENS * VD];
__device__ u16 g_Xn[TOKENS * HID];
__device__ u16 g_P [TOKENS * VD];
__device__ u16 g_Hf[TOKENS * FFND];
__device__ u16 g_Qf[64*4*16384];
__device__ u16 g_Kf[64*4*16384];
__device__ u16 g_Vf[(size_t)64*4*32768];
__device__ u16 g_Wq[4 * HID * QKN];
__device__ u16 g_Wo[4 * VD * HID];
__device__ u16 g_W1[4 * HID * FFND];
__device__ u16 g_W2[4 * FFND * HID];
__device__ float g_qc[LSEQ*16], g_qs[LSEQ*16], g_kc[LSEQ*16], g_ks[LSEQ*16];
__device__ float g_lg2g[4];

__device__ __forceinline__ float geluf(float v){ return 0.5f*v*(1.0f+erff(v*0.70710678f)); }
__device__ __forceinline__ float siluf(float v){ return v/(1.0f+expf(-v)); }
__device__ __forceinline__ unsigned bf2(float a, float b){
    __nv_bfloat162 t = __floats2bfloat162_rn(a, b);
    return *(unsigned*)&t;
}
__device__ __forceinline__ u16 bf1(float a){
    __nv_bfloat16 t = __float2bfloat16_rn(a);
    return *(u16*)&t;
}
__device__ __forceinline__ float2 unbf2(unsigned u){
    __nv_bfloat162 t = *(__nv_bfloat162*)&u;
    return __bfloat1622float2(t);
}
__device__ __forceinline__ void mma_bf16(float* d, const unsigned* a, const unsigned* b){
    asm volatile("mma.sync.aligned.m16n8k16.row.col.f32.bf16.bf16.f32 "
        "{%0,%1,%2,%3},{%4,%5,%6,%7},{%8,%9},{%0,%1,%2,%3};"
        : "+f"(d[0]),"+f"(d[1]),"+f"(d[2]),"+f"(d[3])
        : "r"(a[0]),"r"(a[1]),"r"(a[2]),"r"(a[3]), "r"(b[0]),"r"(b[1]));
}
__device__ __forceinline__ void cpa16(u16* dst, const u16* src){
    unsigned d = (unsigned)__cvta_generic_to_shared(dst);
    asm volatile("cp.async.cg.shared.global [%0], [%1], 16;" :: "r"(d), "l"(src));
}

// A-fragment ushort index, m16n8k16 bf16. Kt = K/16.
__device__ __forceinline__ size_t a16(int row, int k, int Kt){
    return ((size_t)((row>>4)*Kt + (k>>4)))*256 +
           (size_t)(((row&7)*4 + ((k&7)>>1))*8 + (((row>>3)&1) + (((k>>3)&1)<<1))*2 + (k&1));
}
// B-fragment ushort index
__device__ __forceinline__ size_t b16(int k, int n, int Kt){
    return ((size_t)((n>>3)*Kt + (k>>4)))*128 +
           (size_t)(((n&7)*4 + ((k&7)>>1))*4 + (((k>>3)&1)<<1) + (k&1));
}

// ------------------- xpos tables + per-head log2(gamma) -------------------
__global__ void xpos_table_kernel(){
    int idx = blockIdx.x*256 + threadIdx.x;
    if (idx < 4){
        double lgA=-3.4657359027997265, lgB=-6.2383246250395075;
        g_lg2g[idx] = (float)(log(1.0 - exp(lgA + (lgB-lgA)*(double)idx/3.0)) * 1.4426950408889634);
    }
    if (idx >= LSEQ*16) return;
    int l = idx >> 4, j = idx & 15;
    float base = ((float)j + 12.8f) / 44.8f;
    float sc   = powf(base, (float)l / 512.0f);
    float ang  = (float)l * powf(10000.0f, -(float)j/16.0f);
    float s, c; sincosf(ang, &s, &c);
    g_qc[idx]=c*sc; g_qs[idx]=s*sc; g_kc[idx]=c/sc; g_ks[idx]=s/sc;
}

// ------------------- ALL weights -> bf16 B-fragment layout -------------------
__global__ void wfrag_all_kernel(
    const float* __restrict__ wq, const float* __restrict__ wk,
    const float* __restrict__ wv, const float* __restrict__ wg,
    const float* __restrict__ wo, const float* __restrict__ w1,
    const float* __restrict__ w2)
{
    int idx = blockIdx.x*256 + threadIdx.x;
    int l = idx / 196608, r = idx % 196608;
    if (r < 98304){
        int k = r / QKN, n = r % QKN;
        float v;
        if (n < 128)      v = wq[(((size_t)l*4 + (n>>5))*HID + k)*32 + (n&31)];
        else if (n < 256) { int c=n-128; v = wk[(((size_t)l*4 + (c>>5))*HID + k)*32 + (c&31)]; }
        else if (n < 512) { int c=n-256; v = wv[(((size_t)l*4 + (c>>6))*HID + k)*64 + (c&63)]; }
        else              v = wg[((size_t)l*HID + k)*VD + (n-512)];
        g_Wq[(size_t)l*HID*QKN + b16(k, n, 8)] = bf1(v);
    } else {
        int r2 = r - 98304;
        int m = r2 >> 15, e = r2 & 32767;
        if (m == 0){
            int k = e >> 7, n = e & 127;
            g_Wo[(size_t)l*VD*HID + b16(k, n, 16)] =
                bf1(wo[(size_t)l*VD*HID + (size_t)k*HID + n]);
        } else if (m == 1){
            int k = e >> 8, n = e & 255;
            g_W1[(size_t)l*HID*FFND + b16(k, n, 8)] =
                bf1(w1[(size_t)l*HID*FFND + (size_t)k*FFND + n]);
        } else {
            int k = e >> 7, n = e & 127;
            g_W2[(size_t)l*FFND*HID + b16(k, n, 16)] =
                bf1(w2[(size_t)l*FFND*HID + (size_t)k*HID + n]);
        }
    }
}

// ------------------- input MLP -------------------
__global__ __launch_bounds__(256) void rem_kernel(
    const float* __restrict__ x,
    const float* __restrict__ w1, const float* __restrict__ b1,
    const float* __restrict__ w2, const float* __restrict__ b2,
    const float* __restrict__ w3, const float* __restrict__ b3,
    float* __restrict__ X)
{
    __shared__ float sw1[160], sb1[32], sw2[2048], sb2[64], sw3[8192], sb3[128];
    int tid = threadIdx.x;
    for (int i=tid;i<160; i+=256) sw1[i]=w1[i];
    for (int i=tid;i<2048;i+=256) sw2[i]=w2[i];
    for (int i=tid;i<8192;i+=256) sw3[i]=w3[i];
    if (tid<32)  sb1[tid]=b1[tid];
    if (tid<64)  sb2[tid]=b2[tid];
    if (tid<128) sb3[tid]=b3[tid];
    __syncthreads();
    int t = blockIdx.x*256 + tid;
    float xin[5];
#pragma unroll
    for (int k=0;k<5;k++) xin[k] = x[(size_t)t*5+k];
    float h1[32];
#pragma unroll
    for (int o=0;o<32;o++){ float s=sb1[o];
#pragma unroll
        for (int k=0;k<5;k++) s += xin[k]*sw1[k*32+o];
        h1[o]=geluf(s); }
    float h2[64];
#pragma unroll
    for (int o=0;o<64;o++){ float s=sb2[o];
#pragma unroll
        for (int k=0;k<32;k++) s += h1[k]*sw2[k*64+o];
        h2[o]=geluf(s); }
    for (int o=0;o<128;o+=4){
        float v0=sb3[o],v1=sb3[o+1],v2=sb3[o+2],v3=sb3[o+3];
#pragma unroll
        for (int k=0;k<64;k++){ float hk=h2[k];
            v0+=hk*sw3[k*128+o]; v1+=hk*sw3[k*128+o+1];
            v2+=hk*sw3[k*128+o+2]; v3+=hk*sw3[k*128+o+3]; }
        *(float4*)(X+(size_t)t*128+o) = make_float4(geluf(v0),geluf(v1),geluf(v2),geluf(v3));
    }
}

// ------------------- LayerNorm(128) -> bf16 A-fragment layout -------------------
__global__ __launch_bounds__(256) void ln_frag_kernel(
    const float* __restrict__ X, const float* __restrict__ w,
    const float* __restrict__ b, u16* __restrict__ out)
{
    int g = blockIdx.x*256 + threadIdx.x;
    int row = g>>5, lane = g&31;
    float4 v = *(const float4*)(X + (size_t)row*128 + lane*4);
    float s = v.x+v.y+v.z+v.w;
    float s2 = v.x*v.x+v.y*v.y+v.z*v.z+v.w*v.w;
#pragma unroll
    for (int o=16;o;o>>=1){ s += __shfl_xor_sync(~0u,s,o); s2 += __shfl_xor_sync(~0u,s2,o); }
    float mean = s*(1.f/128.f), var = s2*(1.f/128.f)-mean*mean;
    float rstd = rsqrtf(var + 1e-5f);
    float4 wv = *(const float4*)(w+lane*4), bv = *(const float4*)(b+lane*4);
    float rv[4];
    rv[0]=(v.x-mean)*rstd*wv.x+bv.x; rv[1]=(v.y-mean)*rstd*wv.y+bv.y;
    rv[2]=(v.z-mean)*rstd*wv.z+bv.z; rv[3]=(v.w-mean)*rstd*wv.w+bv.w;
    int k0 = lane*4;
    *(unsigned*)(out + a16(row, k0,   8)) = bf2(rv[0], rv[1]);
    *(unsigned*)(out + a16(row, k0+2, 8)) = bf2(rv[2], rv[3]);
}

// ------------------- bf16 frag-fed GEMM, 256x64 block. OP: 1 gelu->Afrag, 3 residual ----
template<int OP>
__global__ __launch_bounds__(256) void gemm_f(
    const u16* __restrict__ Af, const u16* __restrict__ Bf,
    const float* __restrict__ bias, const float* __restrict__ R,
    float* __restrict__ Cf, u16* __restrict__ Ca, int N, int K)
{
    const int tid = threadIdx.x, lane = tid & 31, wid = tid >> 5;
    const int wm = wid & 3, wn = wid >> 2;
    const int m0 = blockIdx.y*256, n0 = blockIdx.x*64;
    const int Kt = K >> 4;

    float acc[4][4][4];
#pragma unroll
    for (int i=0;i<4;i++)
#pragma unroll
        for (int j=0;j<4;j++)
#pragma unroll
            for (int u=0;u<4;u++) acc[i][j][u]=0.f;

    const u16* Ab = Af + ((size_t)((m0>>4) + wm*4))*Kt*256 + lane*8;
    const u16* Bb = Bf + ((size_t)((n0>>3) + wn*4))*Kt*128 + lane*4;

#pragma unroll 2
    for (int kc = 0; kc < Kt; kc++){
        unsigned a[4][4], b[4][2];
#pragma unroll
        for (int mi=0;mi<4;mi++){
            uint4 t = *(const uint4*)(Ab + ((size_t)(mi*Kt + kc))*256);
            a[mi][0]=t.x; a[mi][1]=t.y; a[mi][2]=t.z; a[mi][3]=t.w;
        }
#pragma unroll
        for (int ni=0;ni<4;ni++){
            uint2 t = *(const uint2*)(Bb + ((size_t)(ni*Kt + kc))*128);
            b[ni][0]=t.x; b[ni][1]=t.y;
        }
#pragma unroll
        for (int mi=0;mi<4;mi++)
#pragma unroll
            for (int ni=0;ni<4;ni++)
                mma_bf16(acc[mi][ni], a[mi], b[ni]);
    }

    const int gid = lane>>2, tig = lane&3;
#pragma unroll
    for (int mi=0;mi<4;mi++)
#pragma unroll
        for (int ni=0;ni<4;ni++){
            int col = n0 + wn*32 + ni*8 + tig*2;
            float bb0=0.f, bb1=0.f;
            if (bias){ float2 bv = *(const float2*)(bias+col); bb0=bv.x; bb1=bv.y; }
#pragma unroll
            for (int hh=0; hh<2; hh++){
                int row = m0 + wm*64 + mi*16 + gid + hh*8;
                float v0 = acc[mi][ni][hh*2+0] + bb0;
                float v1 = acc[mi][ni][hh*2+1] + bb1;
                if (OP==1){
                    v0 = geluf(v0); v1 = geluf(v1);
                    *(unsigned*)(Ca + a16(row, col, N>>4)) = bf2(v0, v1);
                } else {
                    float2 rv = *(const float2*)(R + (size_t)row*N + col);
                    v0+=rv.x; v1+=rv.y;
                    *(float2*)(Cf + (size_t)row*N + col) = make_float2(v0,v1);
                }
            }
        }
}

// ------------------- QKVG GEMM: 256x64 block, epilogue -> per-head bf16 frag buffers ----
__global__ __launch_bounds__(256) void gemm_qkvg(
    const u16* __restrict__ Af, const u16* __restrict__ Bf)
{
    const int tid = threadIdx.x, lane = tid & 31, wid = tid >> 5;
    const int wm = wid & 3, wn = wid >> 2;
    const int m0 = blockIdx.y*256, n0 = blockIdx.x*64;
    const int Kt = 8;

    float acc[4][4][4];
#pragma unroll
    for (int i=0;i<4;i++)
#pragma unroll
        for (int j=0;j<4;j++)
#pragma unroll
            for (int u=0;u<4;u++) acc[i][j][u]=0.f;

    const u16* Ab = Af + ((size_t)((m0>>4) + wm*4))*Kt*256 + lane*8;
    const u16* Bb = Bf + ((size_t)((n0>>3) + wn*4))*Kt*128 + lane*4;

#pragma unroll 2
    for (int kc = 0; kc < Kt; kc++){
        unsigned a[4][4], b[4][2];
#pragma unroll
        for (int mi=0;mi<4;mi++){
            uint4 t = *(const uint4*)(Ab + ((size_t)(mi*Kt + kc))*256);
            a[mi][0]=t.x; a[mi][1]=t.y; a[mi][2]=t.z; a[mi][3]=t.w;
        }
#pragma unroll
        for (int ni=0;ni<4;ni++){
            uint2 t = *(const uint2*)(Bb + ((size_t)(ni*Kt + kc))*128);
            b[ni][0]=t.x; b[ni][1]=t.y;
        }
#pragma unroll
        for (int mi=0;mi<4;mi++)
#pragma unroll
            for (int ni=0;ni<4;ni++)
                mma_bf16(acc[mi][ni], a[mi], b[ni]);
    }

    const int gid = lane>>2, tig = lane&3;
#pragma unroll
    for (int mi=0;mi<4;mi++)
#pragma unroll
        for (int ni=0;ni<4;ni++){
            int col = n0 + wn*32 + ni*8 + tig*2;
#pragma unroll
            for (int hh=0; hh<2; hh++){
                int t = m0 + wm*64 + mi*16 + gid + hh*8;
                int bb = t >> 9, ii = t & 511;
                float v0 = acc[mi][ni][hh*2+0];
                float v1 = acc[mi][ni][hh*2+1];
                if (col < 256){
                    const float* ct = (col<128)? g_qc : g_kc;
                    const float* st = (col<128)? g_qs : g_ks;
                    int j = (col&31)>>1;
                    float c0=ct[ii*16+j], s0=st[ii*16+j];
                    float t0 = v0*c0 - v1*s0, t1 = v1*c0 + v0*s0;
                    if (col < 128){
                        int h = col>>5, d = col&31;
                        float sc = exp2f((float)ii * g_lg2g[h]);
                        u16* dst = g_Qf + ((size_t)(bb*4+h))*16384;
                        *(unsigned*)(dst + a16(ii, d, 2)) = bf2(t0*sc, t1*sc);
                    } else {
                        int h = (col-128)>>5, d = (col-128)&31;
                        float sc = exp2f(-(float)ii * g_lg2g[h]);
                        u16* dst = g_Kf + ((size_t)(bb*4+h))*16384;
                        *(unsigned*)(dst + b16(d, ii, 2)) = bf2(t0*sc, t1*sc);
                    }
                } else if (col < 512){
                    int h = (col-256)>>6, v = (col-256)&63;
                    u16* dst = g_Vf + ((size_t)(bb*4+h))*32768;
                    dst[b16(ii, v,   32)] = bf1(v0);
                    dst[b16(ii, v+1, 32)] = bf1(v1);
                } else {
                    *(unsigned*)(g_G + (size_t)t*VD + (col-512)) = bf2(v0, v1);
                }
            }
        }
}

// ------------------- Retention: S in registers, cp.async double-buffered K/V -------------------
// smem: Ks 2x2048 u16 (8KB) @0, Vs 2x4096 u16 (16KB) @8KB -> 24KB
#define RET_SMEM 24576
__global__ __launch_bounds__(256) void retention_kernel(
    const u16* __restrict__ Qf, const u16* __restrict__ Kf,
    const u16* __restrict__ Vf, const u16* __restrict__ G,
    const float* __restrict__ gn_w, const float* __restrict__ gn_b,
    u16* __restrict__ P)
{
    extern __shared__ u16 smu[];
    u16* KsB = smu;          // 2 x 2048
    u16* VsB = smu + 4096;   // 2 x 4096

    const int tid = threadIdx.x, lane = tid&31, wm = tid>>5;
    const int gid = lane>>2, tig = lane&3;
    const int qt = blockIdx.x, h = blockIdx.y, b = blockIdx.z;
    const int l0 = qt*128;
    const size_t rb = (size_t)b*512;
    const size_t bh = (size_t)(b*4 + h);
    const u16* Qg = Qf + bh*16384;
    const u16* Kg = Kf + bh*16384;
    const u16* Vg = Vf + bh*32768;

    // Q fragments -> registers (Kt=2)
    unsigned qf[2][4];
#pragma unroll
    for (int kc=0; kc<2; kc++){
        uint4 t = *(const uint4*)(Qg + ((size_t)(((l0>>4)+wm)*2 + kc))*256 + lane*8);
        qf[kc][0]=t.x; qf[kc][1]=t.y; qf[kc][2]=t.z; qf[kc][3]=t.w;
    }

    float yacc[8][4];
#pragma unroll
    for (int j=0;j<8;j++)
#pragma unroll
        for (int u=0;u<4;u++) yacc[j][u]=0.f;

    const int ntile = 2*qt + 2;
    const int vg0 = tid >> 6, vrem0 = tid & 63;          // V copy index 0 (i4 = tid)
    const int vg1 = (tid+256) >> 6, vrem1 = (tid+256) & 63;

    // stage tile 0 into buffer 0
    {
        cpa16(KsB + tid*8, Kg + (size_t)0*2048 + tid*8);
        cpa16(VsB + (size_t)tid*8,        Vg + ((size_t)(vg0*32 + 0*4)*16 + vrem0)*8);
        cpa16(VsB + (size_t)(tid+256)*8,  Vg + ((size_t)(vg1*32 + 0*4)*16 + vrem1)*8);
        asm volatile("cp.async.commit_group;");
    }

    for (int mt=0; mt<ntile; mt++){
        const int cur = mt & 1;
        const int doff = mt*64 - l0;
        // prefetch next tile into the other buffer
        if (mt+1 < ntile){
            int nb = cur ^ 1;
            cpa16(KsB + nb*2048 + tid*8, Kg + (size_t)(mt+1)*2048 + tid*8);
            cpa16(VsB + nb*4096 + (size_t)tid*8,       Vg + ((size_t)(vg0*32 + (mt+1)*4)*16 + vrem0)*8);
            cpa16(VsB + nb*4096 + (size_t)(tid+256)*8, Vg + ((size_t)(vg1*32 + (mt+1)*4)*16 + vrem1)*8);
            asm volatile("cp.async.commit_group;");
            asm volatile("cp.async.wait_group 1;");
        } else {
            asm volatile("cp.async.wait_group 0;");
        }
        __syncthreads();

        const u16* Ks = KsB + cur*2048;
        const u16* Vs = VsB + cur*4096;

        // S = Q K^T (decay pre-baked), K=32 -> 2 k16-steps
        float sacc[8][4];
#pragma unroll
        for (int j=0;j<8;j++)
#pragma unroll
            for (int u=0;u<4;u++) sacc[j][u]=0.f;
#pragma unroll
        for (int kc=0; kc<2; kc++){
#pragma unroll
            for (int nj=0;nj<8;nj++){
                uint2 bt = *(const uint2*)(Ks + (size_t)(nj*2+kc)*128 + lane*4);
                unsigned bfr[2] = {bt.x, bt.y};
                mma_bf16(sacc[nj], qf[kc], bfr);
            }
        }
        // causal mask in registers
        if (doff >= 0){
#pragma unroll
            for (int nj=0;nj<8;nj++){
                int jb = nj*8 + tig*2 + doff;
#pragma unroll
                for (int ih=0; ih<2; ih++){
                    int i = wm*16 + gid + ih*8;
                    if (i < jb)   sacc[nj][ih*2+0] = 0.f;
                    if (i < jb+1) sacc[nj][ih*2+1] = 0.f;
                }
            }
        }
        // Y += S @ V : pack D-frags directly into A-frags, K=64 -> 4 k16-steps
#pragma unroll
        for (int kc=0; kc<4; kc++){
            unsigned a[4];
            a[0] = bf2(sacc[2*kc  ][0], sacc[2*kc  ][1]);
            a[1] = bf2(sacc[2*kc  ][2], sacc[2*kc  ][3]);
            a[2] = bf2(sacc[2*kc+1][0], sacc[2*kc+1][1]);
            a[3] = bf2(sacc[2*kc+1][2], sacc[2*kc+1][3]);
#pragma unroll
            for (int nj=0;nj<8;nj++){
                uint2 bt = *(const uint2*)(Vs + (size_t)(nj*4+kc)*128 + lane*4);
                unsigned bfr[2] = {bt.x, bt.y};
                mma_bf16(yacc[nj], a, bfr);
            }
        }
        __syncthreads();
    }

    // group-norm + silu gate from registers (warp owns full 64-col rows)
    float s[2]={0.f,0.f}, q[2]={0.f,0.f};
#pragma unroll
    for (int nj=0;nj<8;nj++){
#pragma unroll
        for (int ih=0; ih<2; ih++){
            float v0 = yacc[nj][ih*2+0], v1 = yacc[nj][ih*2+1];
            s[ih] += v0 + v1;
            q[ih] += v0*v0 + v1*v1;
        }
    }
#pragma unroll
    for (int o=1;o<4;o<<=1){
        s[0] += __shfl_xor_sync(~0u, s[0], o);
        q[0] += __shfl_xor_sync(~0u, q[0], o);
        s[1] += __shfl_xor_sync(~0u, s[1], o);
        q[1] += __shfl_xor_sync(~0u, q[1], o);
    }
    float mean[2], rstd[2];
#pragma unroll
    for (int ih=0; ih<2; ih++){
        mean[ih] = s[ih]*(1.f/64.f);
        float var = q[ih]*(1.f/64.f) - mean[ih]*mean[ih];
        rstd[ih] = rsqrtf(var + 1e-5f);
    }
#pragma unroll
    for (int nj=0;nj<8;nj++){
        int col = nj*8 + tig*2;
        int k = h*64 + col;
        float2 wv = *(const float2*)(gn_w + k);
        float2 bv = *(const float2*)(gn_b + k);
#pragma unroll
        for (int ih=0; ih<2; ih++){
            int rowt = (int)(rb + l0 + wm*16 + gid + ih*8);
            unsigned gp = *(const unsigned*)(G + (size_t)rowt*VD + k);
            float2 gg = unbf2(gp);
            float o0 = ((yacc[nj][ih*2+0]-mean[ih])*rstd[ih]*wv.x + bv.x)*siluf(gg.x);
            float o1 = ((yacc[nj][ih*2+1]-mean[ih])*rstd[ih]*wv.y + bv.y)*siluf(gg.y);
            *(unsigned*)(P + a16(rowt, k, 16)) = bf2(o0, o1);
        }
    }
}

// ------------------- decoder + softmax -------------------
__global__ __launch_bounds__(256) void dec_kernel(
    const float* __restrict__ X, const float* __restrict__ w1, const float* __restrict__ b1,
    const float* __restrict__ w2, const float* __restrict__ b2, float* __restrict__ out)
{
    __shared__ float sw1[8192], sw2[1280], sb1[64], sb2[20];
    int tid = threadIdx.x;
    for (int i=tid;i<8192;i+=256) sw1[i]=w1[i];
    for (int i=tid;i<1280;i+=256) sw2[i]=w2[i];
    if (tid<64) sb1[tid]=b1[tid];
    if (tid<20) sb2[tid]=b2[tid];
    __syncthreads();
    int t = blockIdx.x*256 + tid;
    float h[64];
#pragma unroll
    for (int o=0;o<64;o++) h[o]=sb1[o];
    for (int k=0;k<128;k+=4){
        float4 xv = *(const float4*)(X + (size_t)t*128 + k);
#pragma unroll
        for (int o=0;o<64;o++){
            h[o] += xv.x*sw1[(k+0)*64+o] + xv.y*sw1[(k+1)*64+o]
                  + xv.z*sw1[(k+2)*64+o] + xv.w*sw1[(k+3)*64+o];
        }
    }
#pragma unroll
    for (int o=0;o<64;o++) h[o]=geluf(h[o]);
    float lg[20];
#pragma unroll
    for (int o=0;o<20;o++){ float s=sb2[o];
#pragma unroll
        for (int k=0;k<64;k++) s += h[k]*sw2[k*20+o];
        lg[o]=s; }
    float mx = lg[0];
#pragma unroll
    for (int o=1;o<20;o++) mx = fmaxf(mx, lg[o]);
    float sum = 0.f;
#pragma unroll
    for (int o=0;o<20;o++){ lg[o] = expf(lg[o]-mx); sum += lg[o]; }
    float inv = 1.0f/sum;
#pragma unroll
    for (int o=0;o<20;o++) out[(size_t)t*20+o] = lg[o]*inv;
}

// ------------------- launch -------------------
extern "C" void kernel_launch(void* const* d_in, const int* in_sizes, int n_in,
                              void* d_out, int out_size)
{
    const float* x      = (const float*)d_in[0];
    const float* rem_w1 = (const float*)d_in[1];
    const float* rem_b1 = (const float*)d_in[2];
    const float* rem_w2 = (const float*)d_in[3];
    const float* rem_b2 = (const float*)d_in[4];
    const float* rem_w3 = (const float*)d_in[5];
    const float* rem_b3 = (const float*)d_in[6];
    const float* wq     = (const float*)d_in[7];
    const float* wk     = (const float*)d_in[8];
    const float* wv     = (const float*)d_in[9];
    const float* wg     = (const float*)d_in[10];
    const float* wo     = (const float*)d_in[11];
    const float* gn_w   = (const float*)d_in[12];
    const float* gn_b   = (const float*)d_in[13];
    const float* ln1_w  = (const float*)d_in[14];
    const float* ln1_b  = (const float*)d_in[15];
    const float* ln2_w  = (const float*)d_in[16];
    const float* ln2_b  = (const float*)d_in[17];
    const float* ffn_w1 = (const float*)d_in[18];
    const float* ffn_b1 = (const float*)d_in[19];
    const float* ffn_w2 = (const float*)d_in[20];
    const float* ffn_b2 = (const float*)d_in[21];
    const float* dec_w1 = (const float*)d_in[22];
    const float* dec_b1 = (const float*)d_in[23];
    const float* dec_w2 = (const float*)d_in[24];
    const float* dec_b2 = (const float*)d_in[25];
    float* out = (float*)d_out;

    float *pX,*pY1;
    u16 *pG,*pXn,*pP,*pHf,*pWq,*pWo,*pW1,*pW2,*pQf,*pKf,*pVf;
    cudaGetSymbolAddress((void**)&pX,  g_X);
    cudaGetSymbolAddress((void**)&pY1, g_Y1);
    cudaGetSymbolAddress((void**)&pG,  g_G);
    cudaGetSymbolAddress((void**)&pXn, g_Xn);
    cudaGetSymbolAddress((void**)&pP,  g_P);
    cudaGetSymbolAddress((void**)&pHf, g_Hf);
    cudaGetSymbolAddress((void**)&pWq, g_Wq);
    cudaGetSymbolAddress((void**)&pWo, g_Wo);
    cudaGetSymbolAddress((void**)&pW1, g_W1);
    cudaGetSymbolAddress((void**)&pW2, g_W2);
    cudaGetSymbolAddress((void**)&pQf, g_Qf);
    cudaGetSymbolAddress((void**)&pKf, g_Kf);
    cudaGetSymbolAddress((void**)&pVf, g_Vf);

    xpos_table_kernel<<<32, 256>>>();
    wfrag_all_kernel<<<(4*196608)/256, 256>>>(wq, wk, wv, wg, wo, ffn_w1, ffn_w2);
    rem_kernel<<<TOKENS/256, 256>>>(x, rem_w1, rem_b1, rem_w2, rem_b2, rem_w3, rem_b3, pX);

    for (int l = 0; l < 4; l++){
        ln_frag_kernel<<<TOKENS/8, 256>>>(pX, ln1_w + l*128, ln1_b + l*128, pXn);
        gemm_qkvg<<<dim3(QKN/64, TOKENS/256), 256>>>(pXn, pWq + (size_t)l*HID*QKN);
        retention_kernel<<<dim3(4, 4, 64), 256, RET_SMEM>>>(
            pQf, pKf, pVf, pG, gn_w + l*VD, gn_b + l*VD, pP);
        gemm_f<3><<<dim3(HID/64, TOKENS/256), 256>>>(
            pP, pWo + (size_t)l*VD*HID, nullptr, pX, pY1, nullptr, HID, VD);
        ln_frag_kernel<<<TOKENS/8, 256>>>(pY1, ln2_w + l*128, ln2_b + l*128, pXn);
        gemm_f<1><<<dim3(FFND/64, TOKENS/256), 256>>>(
            pXn, pW1 + (size_t)l*HID*FFND, ffn_b1 + l*FFND, nullptr, nullptr, pHf, FFND, HID);
        gemm_f<3><<<dim3(HID/64, TOKENS/256), 256>>>(
            pHf, pW2 + (size_t)l*FFND*HID, ffn_b2 + l*HID, pY1, pX, nullptr, HID, FFND);
    }
    dec_kernel<<<TOKENS/256, 256>>>(pX, dec_w1, dec_b1, dec_w2, dec_b2, out);
}